// round 5
// baseline (speedup 1.0000x reference)
#include <cuda_runtime.h>
#include <math.h>

#define NSTEPS 8192
#define NNODES 4096
#define SG 256
#define NROW 2048
#define DFF 2048
#define H1DIM 512

// h_t for every step (pure function of recurrence, consumed by sampler)
__device__ float g_h_all[NSTEPS * SG];

// ---------------------------------------------------------------------------
// cluster / mbarrier primitives
// ---------------------------------------------------------------------------
__device__ __forceinline__ unsigned smem_u32(const void* p) {
    return (unsigned)__cvta_generic_to_shared(p);
}

__device__ __forceinline__ void st_remote_f32(unsigned laddr, unsigned rank, float v) {
    unsigned r;
    asm volatile("mapa.shared::cluster.u32 %0, %1, %2;" : "=r"(r) : "r"(laddr), "r"(rank));
    asm volatile("st.shared::cluster.f32 [%0], %1;" :: "r"(r), "f"(v) : "memory");
}

__device__ __forceinline__ void arrive_remote(unsigned lmbar, unsigned rank) {
    unsigned r;
    asm volatile("mapa.shared::cluster.u32 %0, %1, %2;" : "=r"(r) : "r"(lmbar), "r"(rank));
    asm volatile("mbarrier.arrive.shared::cluster.b64 _, [%0];" :: "r"(r) : "memory");
}

__device__ __forceinline__ void bar_wait(unsigned mbar, unsigned parity) {
    asm volatile(
        "{\n\t.reg .pred P;\n\t"
        "WL%=:\n\t"
        "mbarrier.try_wait.parity.acquire.cluster.shared::cta.b64 P, [%0], %1, 0x989680;\n\t"
        "@P bra WD%=;\n\t"
        "bra WL%=;\n\t"
        "WD%=:\n\t}"
        :: "r"(mbar), "r"(parity) : "memory");
}

#define CLU_SYNC()                                                        \
    do {                                                                  \
        asm volatile("barrier.cluster.arrive.aligned;" ::: "memory");    \
        asm volatile("barrier.cluster.wait.aligned;" ::: "memory");      \
    } while (0)

// ---------------------------------------------------------------------------
// math helpers (accumulation shapes MUST stay identical across variants)
// ---------------------------------------------------------------------------
__device__ __forceinline__ float warp_reduce(float v) {
#pragma unroll
    for (int o = 16; o; o >>= 1) v += __shfl_xor_sync(0xffffffffu, v, o);
    return v;
}

template <int C>
__device__ __forceinline__ float row_dot(const float* __restrict__ W,
                                         const float* __restrict__ x, int lane) {
    const float4* __restrict__ W4 = reinterpret_cast<const float4*>(W);
    const float4* __restrict__ x4 = reinterpret_cast<const float4*>(x);
    float s = 0.f;
#pragma unroll
    for (int c = 0; c < C / 4; c += 32) {
        float4 w = W4[c + lane];
        float4 xv = x4[c + lane];
        s += w.x * xv.x + w.y * xv.y + w.z * xv.z + w.w * xv.w;
    }
    return warp_reduce(s);
}

// 256-col dot with weights preloaded in registers; same accumulation order.
__device__ __forceinline__ float dot256_reg(const float4* wr,
                                            const float* __restrict__ x, int lane) {
    const float4* __restrict__ x4 = reinterpret_cast<const float4*>(x);
    float s = 0.f;
    float4 xv = x4[lane];
    s += wr[0].x * xv.x + wr[0].y * xv.y + wr[0].z * xv.z + wr[0].w * xv.w;
    xv = x4[32 + lane];
    s += wr[1].x * xv.x + wr[1].y * xv.y + wr[1].z * xv.z + wr[1].w * xv.w;
    return warp_reduce(s);
}

__device__ __forceinline__ void layernorm256(const float* __restrict__ y,
                                             float* __restrict__ out,
                                             const float* __restrict__ gma,
                                             const float* __restrict__ bta,
                                             int tid, float* red) {
    int w = tid >> 5, lane = tid & 31;
    if (w == 0) {
        float s = 0.f;
#pragma unroll
        for (int i = 0; i < 8; ++i) s += y[lane + 32 * i];
        s = warp_reduce(s);
        if (lane == 0) red[0] = s * (1.f / 256.f);
    }
    __syncthreads();
    float mu = red[0];
    if (w == 0) {
        float s = 0.f;
#pragma unroll
        for (int i = 0; i < 8; ++i) {
            float d = y[lane + 32 * i] - mu;
            s += d * d;
        }
        s = warp_reduce(s);
        if (lane == 0) red[1] = 1.f / sqrtf(s * (1.f / 256.f) + 1e-5f);
    }
    __syncthreads();
    float inv = red[1];
    if (tid < 256) out[tid] = (y[tid] - mu) * inv * gma[tid] + bta[tid];
    __syncthreads();
}

// ---------------------------------------------------------------------------
// Cluster-parallel recurrence with DSMEM broadcast + per-stage mbarriers.
// ---------------------------------------------------------------------------
template <int CL>
__global__ void __launch_bounds__(1024, 1) seq_cluster_kernel(
    const float* __restrict__ gnn,
    const float* __restrict__ W1, const float* __restrict__ b1,
    const float* __restrict__ W2, const float* __restrict__ b2,
    const float* __restrict__ Wg, const float* __restrict__ bg,
    const float* __restrict__ Wv, const float* __restrict__ bv,
    const float* __restrict__ Wo, const float* __restrict__ bo,
    const float* __restrict__ Wf1, const float* __restrict__ bf1,
    const float* __restrict__ Wf2, const float* __restrict__ bf2,
    const float* __restrict__ ln1g, const float* __restrict__ ln1b,
    const float* __restrict__ ln2g, const float* __restrict__ ln2b) {
    constexpr int R_H1 = H1DIM / CL;  // 32 (CL16) / 64 (CL8)
    constexpr int R_SG = SG / CL;     // 16 / 32
    constexpr int R_FF = DFF / CL;    // 128 / 256

    __shared__ __align__(16) float cat[H1DIM];   // [m(256); g(256)]
    __shared__ __align__(16) float h1s[H1DIM];
    __shared__ __align__(16) float hs[SG];
    __shared__ __align__(16) float gns[SG];
    __shared__ __align__(16) float vvs[SG];
    __shared__ __align__(16) float ys1[SG];
    __shared__ __align__(16) float xs[SG];
    __shared__ __align__(16) float ff1s[DFF];
    __shared__ __align__(16) float ys2[SG];
    __shared__ __align__(8) unsigned long long mb[7];
    __shared__ float red[2];

    int tid = threadIdx.x, w = tid >> 5, lane = tid & 31;
    unsigned rank;
    asm("mov.u32 %0, %%cluster_ctarank;" : "=r"(rank));

    unsigned a_h1 = smem_u32(h1s), a_hs = smem_u32(hs), a_gns = smem_u32(gns),
             a_vvs = smem_u32(vvs), a_ys1 = smem_u32(ys1), a_ff1 = smem_u32(ff1s),
             a_ys2 = smem_u32(ys2), a_mb = smem_u32(mb);

    // arrivals per consumer barrier = producers(CL) * active warps per producer
    if (tid < 7) {
        const int cnts[7] = {CL * 32, CL * R_SG, CL * R_SG, CL * R_SG,
                             CL * R_SG, CL * 32, CL * R_SG};
        asm volatile("mbarrier.init.shared.b64 [%0], %1;"
                     :: "r"(a_mb + tid * 8), "r"(cnts[tid]) : "memory");
    }
    if (tid < 256) cat[256 + tid] = 0.f;  // g0 = 0
    __syncthreads();
    CLU_SYNC();  // mbarrier inits visible cluster-wide before any remote arrive

    // persistent per-warp state for the 256-row stages (row index == warp id)
    const bool sgact = (w < R_SG);
    const int grs = rank * R_SG + w;
    float4 wgp[2], wvp[2], wop[2];
    float bgv = 0.f, bvv = 0.f, bov = 0.f, b2v = 0.f, bf2v = 0.f;
    if (sgact) {
        const float4* Wg4 = reinterpret_cast<const float4*>(Wg + (size_t)grs * SG);
        const float4* Wv4 = reinterpret_cast<const float4*>(Wv + (size_t)grs * SG);
        const float4* Wo4 = reinterpret_cast<const float4*>(Wo + (size_t)grs * SG);
        wgp[0] = Wg4[lane]; wgp[1] = Wg4[32 + lane];
        wvp[0] = Wv4[lane]; wvp[1] = Wv4[32 + lane];
        wop[0] = Wo4[lane]; wop[1] = Wo4[32 + lane];
        bgv = bg[grs]; bvv = bv[grs]; bov = bo[grs];
        b2v = b2[grs]; bf2v = bf2[grs];
    }

    for (int t = 0; t < NSTEPS; ++t) {
        unsigned par = (unsigned)(t & 1);

        // m = gnn_embeds[t % 4096]
        if (tid < 256) cat[tid] = gnn[(size_t)(t & (NNODES - 1)) * SG + tid];
        __syncthreads();

        // S1: h1 = relu(W1 @ [m;g] + b1) ------------------------------------
#pragma unroll
        for (int r = w; r < R_H1; r += 32) {
            int gr = rank * R_H1 + r;
            float s = row_dot<H1DIM>(W1 + (size_t)gr * H1DIM, cat, lane);
            float v = fmaxf(s + b1[gr], 0.f);
            if (lane < CL) st_remote_f32(a_h1 + 4u * gr, (unsigned)lane, v);
        }
        if (lane < CL) arrive_remote(a_mb + 0 * 8, (unsigned)lane);

        // S2: h = W2 @ h1 + b2 (preload W2 row before waiting on h1) --------
        float4 w2r[4];
        if (sgact) {
            const float4* W24 = reinterpret_cast<const float4*>(W2 + (size_t)grs * H1DIM);
            w2r[0] = W24[lane];      w2r[1] = W24[32 + lane];
            w2r[2] = W24[64 + lane]; w2r[3] = W24[96 + lane];
        }
        bar_wait(a_mb + 0 * 8, par);
        if (sgact) {
            const float4* x4 = reinterpret_cast<const float4*>(h1s);
            float s = 0.f;
            float4 xv;
            xv = x4[lane];      s += w2r[0].x*xv.x + w2r[0].y*xv.y + w2r[0].z*xv.z + w2r[0].w*xv.w;
            xv = x4[32 + lane]; s += w2r[1].x*xv.x + w2r[1].y*xv.y + w2r[1].z*xv.z + w2r[1].w*xv.w;
            xv = x4[64 + lane]; s += w2r[2].x*xv.x + w2r[2].y*xv.y + w2r[2].z*xv.z + w2r[2].w*xv.w;
            xv = x4[96 + lane]; s += w2r[3].x*xv.x + w2r[3].y*xv.y + w2r[3].z*xv.z + w2r[3].w*xv.w;
            s = warp_reduce(s);
            float v = s + b2v;
            if (lane < CL) {
                st_remote_f32(a_hs + 4u * grs, (unsigned)lane, v);
                arrive_remote(a_mb + 1 * 8, (unsigned)lane);
            }
        }
        bar_wait(a_mb + 1 * 8, par);

        // persist h_t for the parallel sampler (write-only STG)
        if (tid < 256) g_h_all[(size_t)t * SG + tid] = hs[tid];

        // S3: gnew = Wg @ h + bg (weights register-resident) ----------------
        if (sgact) {
            float v = dot256_reg(wgp, hs, lane) + bgv;
            if (lane < CL) {
                st_remote_f32(a_gns + 4u * grs, (unsigned)lane, v);
                arrive_remote(a_mb + 2 * 8, (unsigned)lane);
            }
        }
        bar_wait(a_mb + 2 * 8, par);

        // S4: vv = Wv @ gnew + bv -------------------------------------------
        if (sgact) {
            float v = dot256_reg(wvp, gns, lane) + bvv;
            if (lane < CL) {
                st_remote_f32(a_vvs + 4u * grs, (unsigned)lane, v);
                arrive_remote(a_mb + 3 * 8, (unsigned)lane);
            }
        }
        bar_wait(a_mb + 3 * 8, par);

        // S5: y1 = gnew + Wo @ vv + bo --------------------------------------
        if (sgact) {
            float s = dot256_reg(wop, vvs, lane);
            float v = gns[grs] + (s + bov);
            if (lane < CL) {
                st_remote_f32(a_ys1 + 4u * grs, (unsigned)lane, v);
                arrive_remote(a_mb + 4 * 8, (unsigned)lane);
            }
        }
        bar_wait(a_mb + 4 * 8, par);

        // x = LN1(y1) (redundant per CTA, local) ----------------------------
        layernorm256(ys1, xs, ln1g, ln1b, tid, red);

        // S6: ff1 = relu(Wf1 @ x + bf1) -------------------------------------
#pragma unroll
        for (int r = w; r < R_FF; r += 32) {
            int gr = rank * R_FF + r;
            float s = row_dot<SG>(Wf1 + (size_t)gr * SG, xs, lane);
            float v = fmaxf(s + bf1[gr], 0.f);
            if (lane < CL) st_remote_f32(a_ff1 + 4u * gr, (unsigned)lane, v);
        }
        if (lane < CL) arrive_remote(a_mb + 5 * 8, (unsigned)lane);
        bar_wait(a_mb + 5 * 8, par);

        // S7: y2 = x + Wf2 @ ff1 + bf2 --------------------------------------
        if (sgact) {
            float s = row_dot<DFF>(Wf2 + (size_t)grs * DFF, ff1s, lane);
            float v = xs[grs] + (s + bf2v);
            if (lane < CL) {
                st_remote_f32(a_ys2 + 4u * grs, (unsigned)lane, v);
                arrive_remote(a_mb + 6 * 8, (unsigned)lane);
            }
        }
        bar_wait(a_mb + 6 * 8, par);

        // g = LN2(y2) -> cat[256..511] (local) ------------------------------
        layernorm256(ys2, cat + 256, ln2g, ln2b, tid, red);
    }
    CLU_SYNC();  // no CTA exits while peers may still touch its smem
}

// ---------------------------------------------------------------------------
// Sampler: T=8 timesteps per block; per-row dot + sigmoid identical to the
// bit-exact passing version.
// ---------------------------------------------------------------------------
#define SAMP_T 8
#define SAMP_THREADS 512
#define SAMP_SMEM ((SAMP_T * SG + SAMP_T * NROW) * 4)

__global__ void __launch_bounds__(SAMP_THREADS) sample_kernel8(
    const float* __restrict__ u,
    const float* __restrict__ Wr, const float* __restrict__ br,
    float* __restrict__ out) {
    extern __shared__ __align__(16) float sm[];
    float* hsm = sm;                  // [SAMP_T][SG]
    float* probs = sm + SAMP_T * SG;  // [SAMP_T][NROW]
    __shared__ int cnt[SAMP_T][4];
    __shared__ int sel[SAMP_T];

    int tb = blockIdx.x * SAMP_T;
    int tid = threadIdx.x, w = tid >> 5, lane = tid & 31;

    for (int i = tid; i < SAMP_T * SG; i += SAMP_THREADS)
        hsm[i] = g_h_all[(size_t)tb * SG + i];
    if (tid < SAMP_T * 4) cnt[tid >> 2][tid & 3] = 0;
    __syncthreads();

    for (int r = w; r < NROW; r += 16) {
        const float* Wrow = Wr + (size_t)r * SG;
        float brv = br[r];
#pragma unroll
        for (int j = 0; j < SAMP_T; ++j) {
            float s = row_dot<SG>(Wrow, hsm + j * SG, lane);
            if (lane == 0) {
                float z = s + brv;
                float p;
                if (z >= 0.f) {
                    p = 1.f / (1.f + expf(-z));
                } else {
                    float e = expf(z);
                    p = e / (1.f + e);
                }
                probs[j * NROW + r] = p;
            }
        }
    }
    __syncthreads();

#pragma unroll
    for (int j = 0; j < SAMP_T; ++j) {
        const float* __restrict__ ut = u + (size_t)(tb + j) * 4 * NROW;
        int c[4] = {0, 0, 0, 0};
#pragma unroll
        for (int k = 0; k < 4; ++k) {
#pragma unroll
            for (int i = 0; i < NROW / SAMP_THREADS; ++i) {
                int n = tid + SAMP_THREADS * i;
                c[k] += (ut[k * NROW + n] < probs[j * NROW + n]) ? 1 : 0;
            }
        }
#pragma unroll
        for (int k = 0; k < 4; ++k) {
            int s = c[k];
#pragma unroll
            for (int o = 16; o; o >>= 1) s += __shfl_xor_sync(0xffffffffu, s, o);
            if (lane == 0) atomicAdd(&cnt[j][k], s);
        }
    }
    __syncthreads();

    if (tid < SAMP_T) {
        int idx = 0;
        for (int k = 3; k >= 0; --k) {
            int ck = cnt[tid][k];
            bool valid = (ck == 0) || (ck >= 2 && ck <= 6);
            if (valid) idx = k;
        }
        sel[tid] = idx;
    }
    __syncthreads();

#pragma unroll
    for (int j = 0; j < SAMP_T; ++j) {
        const float* __restrict__ ut = u + (size_t)(tb + j) * 4 * NROW;
        int idx = sel[j];
#pragma unroll
        for (int i = 0; i < NROW / SAMP_THREADS; ++i) {
            int n = tid + SAMP_THREADS * i;
            out[(size_t)(tb + j) * NROW + n] =
                (ut[idx * NROW + n] < probs[j * NROW + n]) ? 1.f : 0.f;
        }
    }
}

extern "C" void kernel_launch(void* const* d_in, const int* in_sizes, int n_in,
                              void* d_out, int out_size) {
    (void)in_sizes; (void)n_in; (void)out_size;
    const float* gnn  = (const float*)d_in[0];
    // d_in[1] = b (unused dummy)
    const float* u    = (const float*)d_in[2];
    const float* W1   = (const float*)d_in[3];
    const float* b1   = (const float*)d_in[4];
    const float* W2   = (const float*)d_in[5];
    const float* b2   = (const float*)d_in[6];
    const float* Wr   = (const float*)d_in[7];
    const float* br   = (const float*)d_in[8];
    const float* Wg   = (const float*)d_in[9];
    const float* bg   = (const float*)d_in[10];
    const float* Wv   = (const float*)d_in[11];
    const float* bv   = (const float*)d_in[12];
    const float* Wo   = (const float*)d_in[13];
    const float* bo   = (const float*)d_in[14];
    const float* Wf1  = (const float*)d_in[15];
    const float* bf1  = (const float*)d_in[16];
    const float* Wf2  = (const float*)d_in[17];
    const float* bf2  = (const float*)d_in[18];
    const float* ln1g = (const float*)d_in[19];
    const float* ln1b = (const float*)d_in[20];
    const float* ln2g = (const float*)d_in[21];
    const float* ln2b = (const float*)d_in[22];

    cudaFuncSetAttribute(seq_cluster_kernel<16>,
                         cudaFuncAttributeNonPortableClusterSizeAllowed, 1);
    int maxC = 0;
    {
        cudaLaunchConfig_t q = {};
        q.gridDim = dim3(16, 1, 1);
        q.blockDim = dim3(1024, 1, 1);
        q.dynamicSmemBytes = 0;
        q.stream = 0;
        q.attrs = nullptr;
        q.numAttrs = 0;
        if (cudaOccupancyMaxPotentialClusterSize(&maxC, seq_cluster_kernel<16>, &q)
            != cudaSuccess)
            maxC = 8;
    }

    cudaError_t e = cudaErrorUnknown;
    if (maxC >= 16) {
        cudaLaunchConfig_t cfg = {};
        cfg.gridDim = dim3(16, 1, 1);
        cfg.blockDim = dim3(1024, 1, 1);
        cfg.dynamicSmemBytes = 0;
        cfg.stream = 0;
        cudaLaunchAttribute at[1];
        at[0].id = cudaLaunchAttributeClusterDimension;
        at[0].val.clusterDim.x = 16;
        at[0].val.clusterDim.y = 1;
        at[0].val.clusterDim.z = 1;
        cfg.attrs = at;
        cfg.numAttrs = 1;
        e = cudaLaunchKernelEx(&cfg, seq_cluster_kernel<16>,
                               gnn, W1, b1, W2, b2, Wg, bg, Wv, bv, Wo, bo,
                               Wf1, bf1, Wf2, bf2, ln1g, ln1b, ln2g, ln2b);
    }
    if (e != cudaSuccess) {
        cudaLaunchConfig_t cfg = {};
        cfg.gridDim = dim3(8, 1, 1);
        cfg.blockDim = dim3(1024, 1, 1);
        cfg.dynamicSmemBytes = 0;
        cfg.stream = 0;
        cudaLaunchAttribute at[1];
        at[0].id = cudaLaunchAttributeClusterDimension;
        at[0].val.clusterDim.x = 8;
        at[0].val.clusterDim.y = 1;
        at[0].val.clusterDim.z = 1;
        cfg.attrs = at;
        cfg.numAttrs = 1;
        cudaLaunchKernelEx(&cfg, seq_cluster_kernel<8>,
                           gnn, W1, b1, W2, b2, Wg, bg, Wv, bv, Wo, bo,
                           Wf1, bf1, Wf2, bf2, ln1g, ln1b, ln2g, ln2b);
    }

    cudaFuncSetAttribute(sample_kernel8,
                         cudaFuncAttributeMaxDynamicSharedMemorySize, SAMP_SMEM);
    sample_kernel8<<<NSTEPS / SAMP_T, SAMP_THREADS, SAMP_SMEM>>>(
        u, Wr, br, (float*)d_out);
}

// round 6
// speedup vs baseline: 1.8905x; 1.8905x over previous
#include <cuda_runtime.h>
#include <math.h>

#define NSTEPS 8192
#define NNODES 4096
#define SG 256
#define NROW 2048
#define DFF 2048
#define H1DIM 512

// h_t for every step (bit-exact W2 path; consumed by the sampler kernel)
__device__ float g_h_all[NSTEPS * SG];
// folded matrices (recomputed deterministically every launch)
__device__ float g_A[SG * SG];      // Wo @ Wv
__device__ float g_Bm[SG * SG];     // (I + A) @ Wg
__device__ float g_d[SG];           // (I+A)@bg + Wo@bv + bo
__device__ float g_C[SG * H1DIM];   // Bm @ W2
__device__ float g_e[SG];           // Bm @ b2 + d
// cluster broadcast buffers (global; L2-resident)
__device__ float g_bh1[H1DIM];
__device__ float g_by1[SG];
__device__ float g_bff[DFF];
__device__ float g_by2[SG];

#define CLU_SYNC()                                                        \
    do {                                                                  \
        asm volatile("barrier.cluster.arrive.aligned;" ::: "memory");    \
        asm volatile("barrier.cluster.wait.aligned;" ::: "memory");      \
    } while (0)

__device__ __forceinline__ float warp_reduce(float v) {
#pragma unroll
    for (int o = 16; o; o >>= 1) v += __shfl_xor_sync(0xffffffffu, v, o);
    return v;
}

// dot of one weight row (any addr space, length C) with x (smem, 16B aligned).
// Accumulation shape MUST stay identical across all variants (bit-exactness).
template <int C>
__device__ __forceinline__ float row_dot(const float* __restrict__ W,
                                         const float* __restrict__ x, int lane) {
    const float4* __restrict__ W4 = reinterpret_cast<const float4*>(W);
    const float4* __restrict__ x4 = reinterpret_cast<const float4*>(x);
    float s = 0.f;
#pragma unroll
    for (int c = 0; c < C / 4; c += 32) {
        float4 w = W4[c + lane];
        float4 xv = x4[c + lane];
        s += w.x * xv.x + w.y * xv.y + w.z * xv.z + w.w * xv.w;
    }
    return warp_reduce(s);
}

__device__ __forceinline__ void layernorm256(const float* __restrict__ y,
                                             float* __restrict__ out,
                                             const float* __restrict__ gma,
                                             const float* __restrict__ bta,
                                             int tid, float* red) {
    int w = tid >> 5, lane = tid & 31;
    if (w == 0) {
        float s = 0.f;
#pragma unroll
        for (int i = 0; i < 8; ++i) s += y[lane + 32 * i];
        s = warp_reduce(s);
        if (lane == 0) red[0] = s * (1.f / 256.f);
    }
    __syncthreads();
    float mu = red[0];
    if (w == 0) {
        float s = 0.f;
#pragma unroll
        for (int i = 0; i < 8; ++i) {
            float d = y[lane + 32 * i] - mu;
            s += d * d;
        }
        s = warp_reduce(s);
        if (lane == 0) red[1] = 1.f / sqrtf(s * (1.f / 256.f) + 1e-5f);
    }
    __syncthreads();
    float inv = red[1];
    if (tid < 256) out[tid] = (y[tid] - mu) * inv * gma[tid] + bta[tid];
    __syncthreads();
}

// ---------------------------------------------------------------------------
// Setup kernels: fold the linear chain gnew->attn->residual into C, e.
// ---------------------------------------------------------------------------
__global__ void fold1(const float* __restrict__ Wo, const float* __restrict__ Wv) {
    int i = blockIdx.x, j = threadIdx.x;
    float s = 0.f;
    for (int k = 0; k < SG; ++k) s += Wo[i * SG + k] * Wv[k * SG + j];
    g_A[i * SG + j] = s;
}

__global__ void fold2(const float* __restrict__ Wg, const float* __restrict__ bg,
                      const float* __restrict__ Wo, const float* __restrict__ bv,
                      const float* __restrict__ bo) {
    int i = blockIdx.x, j = threadIdx.x;
    float s = Wg[i * SG + j];
    for (int k = 0; k < SG; ++k) s += g_A[i * SG + k] * Wg[k * SG + j];
    g_Bm[i * SG + j] = s;
    if (j == 0) {
        float t = bg[i] + bo[i];
        for (int k = 0; k < SG; ++k) t += g_A[i * SG + k] * bg[k];
        for (int k = 0; k < SG; ++k) t += Wo[i * SG + k] * bv[k];
        g_d[i] = t;
    }
}

__global__ void fold3(const float* __restrict__ W2, const float* __restrict__ b2) {
    int i = blockIdx.x, j = threadIdx.x;  // 256 blocks x 512 threads
    float s = 0.f;
    for (int k = 0; k < SG; ++k) s += g_Bm[i * SG + k] * W2[k * H1DIM + j];
    g_C[i * H1DIM + j] = s;
    if (j == 0) {
        float t = g_d[i];
        for (int k = 0; k < SG; ++k) t += g_Bm[i * SG + k] * b2[k];
        g_e[i] = t;
    }
}

// ---------------------------------------------------------------------------
// Main chain: 16-CTA cluster, 512 thr/CTA, weights on-chip resident,
// 4 cluster barriers per step.
// ---------------------------------------------------------------------------
#define SEQ_SMEM_FLOATS (32 * H1DIM + 128 * SG + 512 + 512 + 256 + 256 + 2048 + 256)
#define SEQ_SMEM_BYTES (SEQ_SMEM_FLOATS * 4)

__global__ void __launch_bounds__(512, 1) seq16_kernel(
    const float* __restrict__ gnn,
    const float* __restrict__ W1, const float* __restrict__ b1,
    const float* __restrict__ W2, const float* __restrict__ b2,
    const float* __restrict__ Wf1, const float* __restrict__ bf1,
    const float* __restrict__ Wf2, const float* __restrict__ bf2,
    const float* __restrict__ ln1g, const float* __restrict__ ln1b,
    const float* __restrict__ ln2g, const float* __restrict__ ln2b) {
    extern __shared__ __align__(16) float sm[];
    float* w1s  = sm;                 // [32][512]  W1 slice
    float* wf1s = w1s + 32 * H1DIM;   // [128][256] Wf1 slice
    float* cat  = wf1s + 128 * SG;    // [m(256); g(256)]
    float* h1s  = cat + 512;          // 512
    float* ys1  = h1s + 512;          // 256
    float* xs   = ys1 + 256;          // 256
    float* ff1s = xs + 256;           // 2048
    float* ys2  = ff1s + 2048;        // 256
    __shared__ float red[2];

    int tid = threadIdx.x, w = tid >> 5, lane = tid & 31;
    unsigned rank;
    asm("mov.u32 %0, %%cluster_ctarank;" : "=r"(rank));

    // resident smem weights: W1 rows [rank*32,+32), Wf1 rows [rank*128,+128)
    {
        const float4* src = reinterpret_cast<const float4*>(W1 + (size_t)rank * 32 * H1DIM);
        float4* dst = reinterpret_cast<float4*>(w1s);
        for (int i = tid; i < 32 * H1DIM / 4; i += 512) dst[i] = src[i];
        src = reinterpret_cast<const float4*>(Wf1 + (size_t)rank * 128 * SG);
        dst = reinterpret_cast<float4*>(wf1s);
        for (int i = tid; i < 128 * SG / 4; i += 512) dst[i] = src[i];
    }

    // resident register weights: one 256-row per warp
    const int gr = rank * 16 + w;          // row for 256-row stages
    const int g1a = rank * 32 + w, g1b = g1a + 16;  // S1 rows
    float4 w2r[4], crow[4], wf2r[16];
    {
        const float4* W24 = reinterpret_cast<const float4*>(W2 + (size_t)gr * H1DIM);
        w2r[0] = W24[lane];      w2r[1] = W24[32 + lane];
        w2r[2] = W24[64 + lane]; w2r[3] = W24[96 + lane];
        const float4* C4 = reinterpret_cast<const float4*>(g_C + (size_t)gr * H1DIM);
        crow[0] = C4[lane];      crow[1] = C4[32 + lane];
        crow[2] = C4[64 + lane]; crow[3] = C4[96 + lane];
        const float4* Wf24 = reinterpret_cast<const float4*>(Wf2 + (size_t)gr * DFF);
#pragma unroll
        for (int i = 0; i < 16; ++i) wf2r[i] = Wf24[32 * i + lane];
    }
    float b1a = b1[g1a], b1b = b1[g1b];
    float b2v = b2[gr], ev = g_e[gr], bf2v = bf2[gr];
    float bf1r[8];
#pragma unroll
    for (int i = 0; i < 8; ++i) bf1r[i] = bf1[rank * 128 + w + 16 * i];

    if (tid < 256) cat[256 + tid] = 0.f;  // g0 = 0
    __syncthreads();
    CLU_SYNC();

    for (int t = 0; t < NSTEPS; ++t) {
        // m = gnn_embeds[t % 4096]
        if (tid < 256) cat[tid] = gnn[(size_t)(t & (NNODES - 1)) * SG + tid];
        __syncthreads();

        // S1: h1 = relu(W1@[m;g]+b1), 2 rows/warp, weights in smem ----------
        {
            float s0 = row_dot<H1DIM>(w1s + w * H1DIM, cat, lane);
            float v0 = fmaxf(s0 + b1a, 0.f);
            float s1 = row_dot<H1DIM>(w1s + (w + 16) * H1DIM, cat, lane);
            float v1 = fmaxf(s1 + b1b, 0.f);
            if (lane == 0) { g_bh1[g1a] = v0; g_bh1[g1b] = v1; }
        }
        CLU_SYNC();                                    // barrier 1
        h1s[tid] = g_bh1[tid];
        __syncthreads();

        // h = W2@h1 + b2 (bit-exact path for the sampler; NO barrier needed)
        {
            const float4* x4 = reinterpret_cast<const float4*>(h1s);
            float s = 0.f; float4 xv;
            xv = x4[lane];      s += w2r[0].x*xv.x + w2r[0].y*xv.y + w2r[0].z*xv.z + w2r[0].w*xv.w;
            xv = x4[32 + lane]; s += w2r[1].x*xv.x + w2r[1].y*xv.y + w2r[1].z*xv.z + w2r[1].w*xv.w;
            xv = x4[64 + lane]; s += w2r[2].x*xv.x + w2r[2].y*xv.y + w2r[2].z*xv.z + w2r[2].w*xv.w;
            xv = x4[96 + lane]; s += w2r[3].x*xv.x + w2r[3].y*xv.y + w2r[3].z*xv.z + w2r[3].w*xv.w;
            s = warp_reduce(s);
            if (lane == 0) g_h_all[(size_t)t * SG + gr] = s + b2v;
        }

        // y1 = C@h1 + e (folded gnew+attn+residual) -------------------------
        {
            const float4* x4 = reinterpret_cast<const float4*>(h1s);
            float s = 0.f; float4 xv;
            xv = x4[lane];      s += crow[0].x*xv.x + crow[0].y*xv.y + crow[0].z*xv.z + crow[0].w*xv.w;
            xv = x4[32 + lane]; s += crow[1].x*xv.x + crow[1].y*xv.y + crow[1].z*xv.z + crow[1].w*xv.w;
            xv = x4[64 + lane]; s += crow[2].x*xv.x + crow[2].y*xv.y + crow[2].z*xv.z + crow[2].w*xv.w;
            xv = x4[96 + lane]; s += crow[3].x*xv.x + crow[3].y*xv.y + crow[3].z*xv.z + crow[3].w*xv.w;
            s = warp_reduce(s);
            if (lane == 0) g_by1[gr] = s + ev;
        }
        CLU_SYNC();                                    // barrier 2
        if (tid < 256) ys1[tid] = g_by1[tid];
        __syncthreads();

        // x = LN1(y1) (local, redundant per CTA)
        layernorm256(ys1, xs, ln1g, ln1b, tid, red);

        // S6: ff1 = relu(Wf1@x + bf1), 8 rows/warp, weights in smem ---------
#pragma unroll
        for (int i = 0; i < 8; ++i) {
            int r = w + 16 * i;
            float s = row_dot<SG>(wf1s + r * SG, xs, lane);
            if (lane == 0) g_bff[rank * 128 + r] = fmaxf(s + bf1r[i], 0.f);
        }
        CLU_SYNC();                                    // barrier 3
        for (int i = tid; i < DFF; i += 512) ff1s[i] = g_bff[i];
        __syncthreads();

        // S7: y2 = x + Wf2@ff1 + bf2, weights in registers ------------------
        {
            const float4* x4 = reinterpret_cast<const float4*>(ff1s);
            float s = 0.f;
#pragma unroll
            for (int i = 0; i < 16; ++i) {
                float4 xv = x4[32 * i + lane];
                s += wf2r[i].x*xv.x + wf2r[i].y*xv.y + wf2r[i].z*xv.z + wf2r[i].w*xv.w;
            }
            s = warp_reduce(s);
            if (lane == 0) g_by2[gr] = xs[gr] + (s + bf2v);
        }
        CLU_SYNC();                                    // barrier 4
        if (tid < 256) ys2[tid] = g_by2[tid];
        __syncthreads();

        // g = LN2(y2) -> cat[256..511] (local)
        layernorm256(ys2, cat + 256, ln2g, ln2b, tid, red);
    }
    CLU_SYNC();
}

// ---------------------------------------------------------------------------
// Fallback (cluster size < 16): R4-proven streaming kernel, CL=8.
// ---------------------------------------------------------------------------
__global__ void __launch_bounds__(1024, 1) seq_fallback8(
    const float* __restrict__ gnn,
    const float* __restrict__ W1, const float* __restrict__ b1,
    const float* __restrict__ W2, const float* __restrict__ b2,
    const float* __restrict__ Wg, const float* __restrict__ bg,
    const float* __restrict__ Wv, const float* __restrict__ bv,
    const float* __restrict__ Wo, const float* __restrict__ bo,
    const float* __restrict__ Wf1, const float* __restrict__ bf1,
    const float* __restrict__ Wf2, const float* __restrict__ bf2,
    const float* __restrict__ ln1g, const float* __restrict__ ln1b,
    const float* __restrict__ ln2g, const float* __restrict__ ln2b) {
    constexpr int CL = 8;
    constexpr int R_H1 = H1DIM / CL, R_SG = SG / CL, R_FF = DFF / CL;
    __shared__ __align__(16) float cat[H1DIM];
    __shared__ __align__(16) float h1s[H1DIM];
    __shared__ __align__(16) float hs[SG];
    __shared__ __align__(16) float gns[SG];
    __shared__ __align__(16) float vvs[SG];
    __shared__ __align__(16) float ys[SG];
    __shared__ __align__(16) float xs[SG];
    __shared__ __align__(16) float ff1s[DFF];
    __shared__ float red[2];

    int tid = threadIdx.x, w = tid >> 5, lane = tid & 31;
    unsigned rank;
    asm("mov.u32 %0, %%cluster_ctarank;" : "=r"(rank));
    if (tid < 256) cat[256 + tid] = 0.f;
    __syncthreads();

    for (int t = 0; t < NSTEPS; ++t) {
        if (tid < 256) cat[tid] = gnn[(size_t)(t & (NNODES - 1)) * SG + tid];
        __syncthreads();
        for (int r = w; r < R_H1; r += 32) {
            int gr = rank * R_H1 + r;
            float s = row_dot<H1DIM>(W1 + (size_t)gr * H1DIM, cat, lane);
            if (lane == 0) g_bh1[gr] = fmaxf(s + b1[gr], 0.f);
        }
        CLU_SYNC();
        for (int i = tid; i < H1DIM; i += 1024) h1s[i] = g_bh1[i];
        __syncthreads();
        float* gh = g_h_all + (size_t)t * SG;
        for (int r = w; r < R_SG; r += 32) {
            int gr = rank * R_SG + r;
            float s = row_dot<H1DIM>(W2 + (size_t)gr * H1DIM, h1s, lane);
            if (lane == 0) gh[gr] = s + b2[gr];
        }
        CLU_SYNC();
        for (int i = tid; i < SG; i += 1024) hs[i] = gh[i];
        __syncthreads();
        for (int r = w; r < R_SG; r += 32) {
            int gr = rank * R_SG + r;
            float s = row_dot<SG>(Wg + (size_t)gr * SG, hs, lane);
            if (lane == 0) g_by1[gr] = s + bg[gr];
        }
        CLU_SYNC();
        for (int i = tid; i < SG; i += 1024) gns[i] = g_by1[i];
        __syncthreads();
        for (int r = w; r < R_SG; r += 32) {
            int gr = rank * R_SG + r;
            float s = row_dot<SG>(Wv + (size_t)gr * SG, gns, lane);
            if (lane == 0) g_by2[gr] = s + bv[gr];
        }
        CLU_SYNC();
        for (int i = tid; i < SG; i += 1024) vvs[i] = g_by2[i];
        __syncthreads();
        for (int r = w; r < R_SG; r += 32) {
            int gr = rank * R_SG + r;
            float s = row_dot<SG>(Wo + (size_t)gr * SG, vvs, lane);
            if (lane == 0) g_by1[gr] = gns[gr] + (s + bo[gr]);
        }
        CLU_SYNC();
        for (int i = tid; i < SG; i += 1024) ys[i] = g_by1[i];
        __syncthreads();
        layernorm256(ys, xs, ln1g, ln1b, tid, red);
        for (int r = w; r < R_FF; r += 32) {
            int gr = rank * R_FF + r;
            float s = row_dot<SG>(Wf1 + (size_t)gr * SG, xs, lane);
            if (lane == 0) g_bff[gr] = fmaxf(s + bf1[gr], 0.f);
        }
        CLU_SYNC();
        for (int i = tid; i < DFF; i += 1024) ff1s[i] = g_bff[i];
        __syncthreads();
        for (int r = w; r < R_SG; r += 32) {
            int gr = rank * R_SG + r;
            float s = row_dot<DFF>(Wf2 + (size_t)gr * DFF, ff1s, lane);
            if (lane == 0) g_by2[gr] = xs[gr] + (s + bf2[gr]);
        }
        CLU_SYNC();
        for (int i = tid; i < SG; i += 1024) ys[i] = g_by2[i];
        __syncthreads();
        layernorm256(ys, cat + 256, ln2g, ln2b, tid, red);
    }
}

// ---------------------------------------------------------------------------
// Sampler (bit-exact): T=8 timesteps per block.
// ---------------------------------------------------------------------------
#define SAMP_T 8
#define SAMP_THREADS 512
#define SAMP_SMEM ((SAMP_T * SG + SAMP_T * NROW) * 4)

__global__ void __launch_bounds__(SAMP_THREADS) sample_kernel8(
    const float* __restrict__ u,
    const float* __restrict__ Wr, const float* __restrict__ br,
    float* __restrict__ out) {
    extern __shared__ __align__(16) float sm[];
    float* hsm = sm;
    float* probs = sm + SAMP_T * SG;
    __shared__ int cnt[SAMP_T][4];
    __shared__ int sel[SAMP_T];

    int tb = blockIdx.x * SAMP_T;
    int tid = threadIdx.x, w = tid >> 5, lane = tid & 31;

    for (int i = tid; i < SAMP_T * SG; i += SAMP_THREADS)
        hsm[i] = g_h_all[(size_t)tb * SG + i];
    if (tid < SAMP_T * 4) cnt[tid >> 2][tid & 3] = 0;
    __syncthreads();

    for (int r = w; r < NROW; r += 16) {
        const float* Wrow = Wr + (size_t)r * SG;
        float brv = br[r];
#pragma unroll
        for (int j = 0; j < SAMP_T; ++j) {
            float s = row_dot<SG>(Wrow, hsm + j * SG, lane);
            if (lane == 0) {
                float z = s + brv;
                float p;
                if (z >= 0.f) {
                    p = 1.f / (1.f + expf(-z));
                } else {
                    float e = expf(z);
                    p = e / (1.f + e);
                }
                probs[j * NROW + r] = p;
            }
        }
    }
    __syncthreads();

#pragma unroll
    for (int j = 0; j < SAMP_T; ++j) {
        const float* __restrict__ ut = u + (size_t)(tb + j) * 4 * NROW;
        int c[4] = {0, 0, 0, 0};
#pragma unroll
        for (int k = 0; k < 4; ++k)
#pragma unroll
            for (int i = 0; i < NROW / SAMP_THREADS; ++i) {
                int n = tid + SAMP_THREADS * i;
                c[k] += (ut[k * NROW + n] < probs[j * NROW + n]) ? 1 : 0;
            }
#pragma unroll
        for (int k = 0; k < 4; ++k) {
            int s = c[k];
#pragma unroll
            for (int o = 16; o; o >>= 1) s += __shfl_xor_sync(0xffffffffu, s, o);
            if (lane == 0) atomicAdd(&cnt[j][k], s);
        }
    }
    __syncthreads();

    if (tid < SAMP_T) {
        int idx = 0;
        for (int k = 3; k >= 0; --k) {
            int ck = cnt[tid][k];
            bool valid = (ck == 0) || (ck >= 2 && ck <= 6);
            if (valid) idx = k;
        }
        sel[tid] = idx;
    }
    __syncthreads();

#pragma unroll
    for (int j = 0; j < SAMP_T; ++j) {
        const float* __restrict__ ut = u + (size_t)(tb + j) * 4 * NROW;
        int idx = sel[j];
#pragma unroll
        for (int i = 0; i < NROW / SAMP_THREADS; ++i) {
            int n = tid + SAMP_THREADS * i;
            out[(size_t)(tb + j) * NROW + n] =
                (ut[idx * NROW + n] < probs[j * NROW + n]) ? 1.f : 0.f;
        }
    }
}

extern "C" void kernel_launch(void* const* d_in, const int* in_sizes, int n_in,
                              void* d_out, int out_size) {
    (void)in_sizes; (void)n_in; (void)out_size;
    const float* gnn  = (const float*)d_in[0];
    const float* u    = (const float*)d_in[2];
    const float* W1   = (const float*)d_in[3];
    const float* b1   = (const float*)d_in[4];
    const float* W2   = (const float*)d_in[5];
    const float* b2   = (const float*)d_in[6];
    const float* Wr   = (const float*)d_in[7];
    const float* br   = (const float*)d_in[8];
    const float* Wg   = (const float*)d_in[9];
    const float* bg   = (const float*)d_in[10];
    const float* Wv   = (const float*)d_in[11];
    const float* bv   = (const float*)d_in[12];
    const float* Wo   = (const float*)d_in[13];
    const float* bo   = (const float*)d_in[14];
    const float* Wf1  = (const float*)d_in[15];
    const float* bf1  = (const float*)d_in[16];
    const float* Wf2  = (const float*)d_in[17];
    const float* bf2  = (const float*)d_in[18];
    const float* ln1g = (const float*)d_in[19];
    const float* ln1b = (const float*)d_in[20];
    const float* ln2g = (const float*)d_in[21];
    const float* ln2b = (const float*)d_in[22];

    // fold the linear sub-chain (deterministic, every call)
    fold1<<<SG, SG>>>(Wo, Wv);
    fold2<<<SG, SG>>>(Wg, bg, Wo, bv, bo);
    fold3<<<SG, H1DIM>>>(W2, b2);

    cudaFuncSetAttribute(seq16_kernel,
                         cudaFuncAttributeMaxDynamicSharedMemorySize, SEQ_SMEM_BYTES);
    cudaFuncSetAttribute(seq16_kernel,
                         cudaFuncAttributeNonPortableClusterSizeAllowed, 1);

    cudaError_t e = cudaErrorUnknown;
    {
        cudaLaunchConfig_t cfg = {};
        cfg.gridDim = dim3(16, 1, 1);
        cfg.blockDim = dim3(512, 1, 1);
        cfg.dynamicSmemBytes = SEQ_SMEM_BYTES;
        cfg.stream = 0;
        cudaLaunchAttribute at[1];
        at[0].id = cudaLaunchAttributeClusterDimension;
        at[0].val.clusterDim.x = 16;
        at[0].val.clusterDim.y = 1;
        at[0].val.clusterDim.z = 1;
        cfg.attrs = at;
        cfg.numAttrs = 1;
        e = cudaLaunchKernelEx(&cfg, seq16_kernel,
                               gnn, W1, b1, W2, b2, Wf1, bf1, Wf2, bf2,
                               ln1g, ln1b, ln2g, ln2b);
    }
    if (e != cudaSuccess) {
        cudaLaunchConfig_t cfg = {};
        cfg.gridDim = dim3(8, 1, 1);
        cfg.blockDim = dim3(1024, 1, 1);
        cfg.dynamicSmemBytes = 0;
        cfg.stream = 0;
        cudaLaunchAttribute at[1];
        at[0].id = cudaLaunchAttributeClusterDimension;
        at[0].val.clusterDim.x = 8;
        at[0].val.clusterDim.y = 1;
        at[0].val.clusterDim.z = 1;
        cfg.attrs = at;
        cfg.numAttrs = 1;
        cudaLaunchKernelEx(&cfg, seq_fallback8,
                           gnn, W1, b1, W2, b2, Wg, bg, Wv, bv, Wo, bo,
                           Wf1, bf1, Wf2, bf2, ln1g, ln1b, ln2g, ln2b);
    }

    cudaFuncSetAttribute(sample_kernel8,
                         cudaFuncAttributeMaxDynamicSharedMemorySize, SAMP_SMEM);
    sample_kernel8<<<NSTEPS / SAMP_T, SAMP_THREADS, SAMP_SMEM>>>(
        u, Wr, br, (float*)d_out);
}

// round 7
// speedup vs baseline: 2.5031x; 1.3240x over previous
#include <cuda_runtime.h>
#include <math.h>

#define NSTEPS 8192
#define NNODES 4096
#define SG 256
#define NROW 2048
#define DFF 2048
#define H1DIM 512

// h_t for every step (consumed by the sampler kernel)
__device__ float g_h_all[NSTEPS * SG];
// folded matrices (recomputed deterministically every launch)
__device__ float g_A[SG * SG];      // Wo @ Wv
__device__ float g_Bm[SG * SG];     // (I + A) @ Wg
__device__ float g_d[SG];           // (I+A)@bg + Wo@bv + bo
__device__ float g_C[SG * H1DIM];   // Bm @ W2
__device__ float g_e[SG];           // Bm @ b2 + d
// cross-CTA partial buffers (L2-resident)
__device__ float g_p1[16 * SG];     // y1 partials
__device__ float g_ph[16 * SG];     // h partials
__device__ float g_p2[16 * SG];     // y2 partials
// fallback broadcast buffers
__device__ float g_bh1[H1DIM];
__device__ float g_by1[SG];
__device__ float g_bff[DFF];
__device__ float g_by2[SG];

#define CLU_SYNC()                                                        \
    do {                                                                  \
        asm volatile("barrier.cluster.arrive.aligned;" ::: "memory");    \
        asm volatile("barrier.cluster.wait.aligned;" ::: "memory");      \
    } while (0)

__device__ __forceinline__ float warp_reduce(float v) {
#pragma unroll
    for (int o = 16; o; o >>= 1) v += __shfl_xor_sync(0xffffffffu, v, o);
    return v;
}

template <int C>
__device__ __forceinline__ float row_dot(const float* __restrict__ W,
                                         const float* __restrict__ x, int lane) {
    const float4* __restrict__ W4 = reinterpret_cast<const float4*>(W);
    const float4* __restrict__ x4 = reinterpret_cast<const float4*>(x);
    float s = 0.f;
#pragma unroll
    for (int c = 0; c < C / 4; c += 32) {
        float4 w = W4[c + lane];
        float4 xv = x4[c + lane];
        s += w.x * xv.x + w.y * xv.y + w.z * xv.z + w.w * xv.w;
    }
    return warp_reduce(s);
}

__device__ __forceinline__ void layernorm256(const float* __restrict__ y,
                                             float* __restrict__ out,
                                             const float* __restrict__ gma,
                                             const float* __restrict__ bta,
                                             int tid, float* red) {
    int w = tid >> 5, lane = tid & 31;
    if (w == 0) {
        float s = 0.f;
#pragma unroll
        for (int i = 0; i < 8; ++i) s += y[lane + 32 * i];
        s = warp_reduce(s);
        if (lane == 0) red[0] = s * (1.f / 256.f);
    }
    __syncthreads();
    float mu = red[0];
    if (w == 0) {
        float s = 0.f;
#pragma unroll
        for (int i = 0; i < 8; ++i) {
            float d = y[lane + 32 * i] - mu;
            s += d * d;
        }
        s = warp_reduce(s);
        if (lane == 0) red[1] = 1.f / sqrtf(s * (1.f / 256.f) + 1e-5f);
    }
    __syncthreads();
    float inv = red[1];
    if (tid < 256) out[tid] = (y[tid] - mu) * inv * gma[tid] + bta[tid];
    __syncthreads();
}

// ---------------------------------------------------------------------------
// Setup kernels: fold gnew->attn->residual into C, e.
// ---------------------------------------------------------------------------
__global__ void fold1(const float* __restrict__ Wo, const float* __restrict__ Wv) {
    int i = blockIdx.x, j = threadIdx.x;
    float s = 0.f;
    for (int k = 0; k < SG; ++k) s += Wo[i * SG + k] * Wv[k * SG + j];
    g_A[i * SG + j] = s;
}

__global__ void fold2(const float* __restrict__ Wg, const float* __restrict__ bg,
                      const float* __restrict__ Wo, const float* __restrict__ bv,
                      const float* __restrict__ bo) {
    int i = blockIdx.x, j = threadIdx.x;
    float s = Wg[i * SG + j];
    for (int k = 0; k < SG; ++k) s += g_A[i * SG + k] * Wg[k * SG + j];
    g_Bm[i * SG + j] = s;
    if (j == 0) {
        float t = bg[i] + bo[i];
        for (int k = 0; k < SG; ++k) t += g_A[i * SG + k] * bg[k];
        for (int k = 0; k < SG; ++k) t += Wo[i * SG + k] * bv[k];
        g_d[i] = t;
    }
}

__global__ void fold3(const float* __restrict__ W2, const float* __restrict__ b2) {
    int i = blockIdx.x, j = threadIdx.x;
    float s = 0.f;
    for (int k = 0; k < SG; ++k) s += g_Bm[i * SG + k] * W2[k * H1DIM + j];
    g_C[i * H1DIM + j] = s;
    if (j == 0) {
        float t = g_d[i];
        for (int k = 0; k < SG; ++k) t += g_Bm[i * SG + k] * b2[k];
        g_e[i] = t;
    }
}

// ---------------------------------------------------------------------------
// Main chain: 16-CTA cluster, 512 thr/CTA, 2 cluster barriers per step.
// Column-sliced partial sums for (h, y1) and y2.
// ---------------------------------------------------------------------------
#define SEQ2_SMEM_FLOATS (32 * H1DIM + 128 * SG + 512 + 32 + 256 + 256 + 128 + 512)
#define SEQ2_SMEM_BYTES (SEQ2_SMEM_FLOATS * 4)

__global__ void __launch_bounds__(512, 1) seq2_kernel(
    const float* __restrict__ gnn,
    const float* __restrict__ W1, const float* __restrict__ b1,
    const float* __restrict__ W2, const float* __restrict__ b2,
    const float* __restrict__ Wf1, const float* __restrict__ bf1,
    const float* __restrict__ Wf2, const float* __restrict__ bf2,
    const float* __restrict__ ln1g, const float* __restrict__ ln1b,
    const float* __restrict__ ln2g, const float* __restrict__ ln2b) {
    extern __shared__ __align__(16) float sm[];
    float* w1s   = sm;                  // [32][512]  W1 row slice
    float* wf1s  = w1s + 32 * H1DIM;    // [128][256] Wf1 row slice
    float* cat   = wf1s + 128 * SG;     // [m(256); g(256)]
    float* h1loc = cat + 512;           // 32  : this CTA's h1 slice
    float* xs    = h1loc + 32;          // 256
    float* ys    = xs + 256;            // 256 (y1 / y2, time-shared)
    float* ffloc = ys + 256;            // 128 : this CTA's ff slice
    float* p2tmp = ffloc + 128;         // 512
    __shared__ float red[2];

    int tid = threadIdx.x, w = tid >> 5, lane = tid & 31;
    unsigned rank;
    asm("mov.u32 %0, %%cluster_ctarank;" : "=r"(rank));

    // resident smem weights: W1 rows [rank*32,+32), Wf1 rows [rank*128,+128)
    {
        const float4* src = reinterpret_cast<const float4*>(W1 + (size_t)rank * 32 * H1DIM);
        float4* dst = reinterpret_cast<float4*>(w1s);
        for (int i = tid; i < 32 * H1DIM / 4; i += 512) dst[i] = src[i];
        src = reinterpret_cast<const float4*>(Wf1 + (size_t)rank * 128 * SG);
        dst = reinterpret_cast<float4*>(wf1s);
        for (int i = tid; i < 128 * SG / 4; i += 512) dst[i] = src[i];
    }

    // ---- persistent register weights -------------------------------------
    // partial-1: tid<256 -> h partial (W2 columns), tid>=256 -> y1 partial (C cols)
    float pw[32];
    {
        const float* psrc = (tid < 256)
            ? (W2 + (size_t)tid * H1DIM + rank * 32)
            : (g_C + (size_t)(tid - 256) * H1DIM + rank * 32);
#pragma unroll
        for (int c = 0; c < 32; ++c) pw[c] = psrc[c];
    }
    // partial-2: Wf2 column slice; thread (r = tid&255, half = tid>>8) covers 64 cols
    float wf2c[64];
    {
        int r2 = tid & 255, half = tid >> 8;
        const float* wsrc = Wf2 + (size_t)r2 * DFF + rank * 128 + half * 64;
#pragma unroll
        for (int c = 0; c < 64; ++c) wf2c[c] = wsrc[c];
    }
    // scalars
    const int g1a = rank * 32 + w, g1b = g1a + 16;  // S1 rows for this warp
    float b1a = b1[g1a], b1b = b1[g1b];
    float bf1r[8];
#pragma unroll
    for (int i = 0; i < 8; ++i) bf1r[i] = bf1[rank * 128 + w + 16 * i];
    float e_r = (tid < 256) ? g_e[tid] : 0.f;
    float bf2_r = (tid < 256) ? bf2[tid] : 0.f;
    float b2row = 0.f;
    int hrow = -1;
    if (tid >= 256 && tid < 256 + 16) {
        hrow = rank * 16 + (tid - 256);
        b2row = b2[hrow];
    }

    if (tid < 256) cat[256 + tid] = 0.f;  // g0 = 0
    __syncthreads();
    CLU_SYNC();

    for (int t = 0; t < NSTEPS; ++t) {
        // m = gnn_embeds[t % 4096]
        if (tid < 256) cat[tid] = gnn[(size_t)(t & (NNODES - 1)) * SG + tid];
        __syncthreads();

        // S1: h1 slice = relu(W1@[m;g]+b1), 2 rows/warp, weights in smem
        {
            float s0 = row_dot<H1DIM>(w1s + w * H1DIM, cat, lane);
            float v0 = fmaxf(s0 + b1a, 0.f);
            float s1 = row_dot<H1DIM>(w1s + (w + 16) * H1DIM, cat, lane);
            float v1 = fmaxf(s1 + b1b, 0.f);
            if (lane == 0) { h1loc[w] = v0; h1loc[w + 16] = v1; }
        }
        __syncthreads();

        // partial-1: every thread does one 32-col dot against local h1 slice
        {
            float acc = 0.f;
#pragma unroll
            for (int c = 0; c < 32; ++c) acc += pw[c] * h1loc[c];
            if (tid < 256) g_ph[rank * SG + tid] = acc;
            else           g_p1[rank * SG + (tid - 256)] = acc;
        }
        CLU_SYNC();                                     // barrier 1

        // reduce (fixed k order, deterministic)
        if (tid < 256) {
            float s = e_r;
#pragma unroll
            for (int k = 0; k < 16; ++k) s += g_p1[k * SG + tid];
            ys[tid] = s;                                // y1 (full, replicated)
        } else if (hrow >= 0) {
            float s = b2row;
#pragma unroll
            for (int k = 0; k < 16; ++k) s += g_ph[k * SG + hrow];
            g_h_all[(size_t)t * SG + hrow] = s;         // h row for the sampler
        }
        __syncthreads();

        // x = LN1(y1) (replicated, local)
        layernorm256(ys, xs, ln1g, ln1b, tid, red);

        // ff slice = relu(Wf1@x + bf1), 8 rows/warp, weights in smem; stays local
#pragma unroll
        for (int i = 0; i < 8; ++i) {
            int r = w + 16 * i;
            float s = row_dot<SG>(wf1s + r * SG, xs, lane);
            if (lane == 0) ffloc[r] = fmaxf(s + bf1r[i], 0.f);
        }
        __syncthreads();

        // partial-2: y2 partial = Wf2[:, my 128 cols] @ ffloc
        {
            int half = tid >> 8;
            const float* fl = ffloc + half * 64;
            float a2 = 0.f;
#pragma unroll
            for (int c = 0; c < 64; ++c) a2 += wf2c[c] * fl[c];
            p2tmp[tid] = a2;
        }
        __syncthreads();
        if (tid < 256) g_p2[rank * SG + tid] = p2tmp[tid] + p2tmp[tid + 256];
        CLU_SYNC();                                     // barrier 2

        if (tid < 256) {
            float s = xs[tid] + bf2_r;
#pragma unroll
            for (int k = 0; k < 16; ++k) s += g_p2[k * SG + tid];
            ys[tid] = s;                                // y2 (full, replicated)
        }
        __syncthreads();

        // g = LN2(y2) -> cat[256..511]
        layernorm256(ys, cat + 256, ln2g, ln2b, tid, red);
    }
    CLU_SYNC();
}

// ---------------------------------------------------------------------------
// Fallback (cluster size < 16): R4-proven streaming kernel, CL=8.
// ---------------------------------------------------------------------------
__global__ void __launch_bounds__(1024, 1) seq_fallback8(
    const float* __restrict__ gnn,
    const float* __restrict__ W1, const float* __restrict__ b1,
    const float* __restrict__ W2, const float* __restrict__ b2,
    const float* __restrict__ Wg, const float* __restrict__ bg,
    const float* __restrict__ Wv, const float* __restrict__ bv,
    const float* __restrict__ Wo, const float* __restrict__ bo,
    const float* __restrict__ Wf1, const float* __restrict__ bf1,
    const float* __restrict__ Wf2, const float* __restrict__ bf2,
    const float* __restrict__ ln1g, const float* __restrict__ ln1b,
    const float* __restrict__ ln2g, const float* __restrict__ ln2b) {
    constexpr int CL = 8;
    constexpr int R_H1 = H1DIM / CL, R_SG = SG / CL, R_FF = DFF / CL;
    __shared__ __align__(16) float cat[H1DIM];
    __shared__ __align__(16) float h1s[H1DIM];
    __shared__ __align__(16) float hs[SG];
    __shared__ __align__(16) float gns[SG];
    __shared__ __align__(16) float vvs[SG];
    __shared__ __align__(16) float ys[SG];
    __shared__ __align__(16) float xs[SG];
    __shared__ __align__(16) float ff1s[DFF];
    __shared__ float red[2];

    int tid = threadIdx.x, w = tid >> 5, lane = tid & 31;
    unsigned rank;
    asm("mov.u32 %0, %%cluster_ctarank;" : "=r"(rank));
    if (tid < 256) cat[256 + tid] = 0.f;
    __syncthreads();

    for (int t = 0; t < NSTEPS; ++t) {
        if (tid < 256) cat[tid] = gnn[(size_t)(t & (NNODES - 1)) * SG + tid];
        __syncthreads();
        for (int r = w; r < R_H1; r += 32) {
            int gr = rank * R_H1 + r;
            float s = row_dot<H1DIM>(W1 + (size_t)gr * H1DIM, cat, lane);
            if (lane == 0) g_bh1[gr] = fmaxf(s + b1[gr], 0.f);
        }
        CLU_SYNC();
        for (int i = tid; i < H1DIM; i += 1024) h1s[i] = g_bh1[i];
        __syncthreads();
        float* gh = g_h_all + (size_t)t * SG;
        for (int r = w; r < R_SG; r += 32) {
            int gr = rank * R_SG + r;
            float s = row_dot<H1DIM>(W2 + (size_t)gr * H1DIM, h1s, lane);
            if (lane == 0) gh[gr] = s + b2[gr];
        }
        CLU_SYNC();
        for (int i = tid; i < SG; i += 1024) hs[i] = gh[i];
        __syncthreads();
        for (int r = w; r < R_SG; r += 32) {
            int gr = rank * R_SG + r;
            float s = row_dot<SG>(Wg + (size_t)gr * SG, hs, lane);
            if (lane == 0) g_by1[gr] = s + bg[gr];
        }
        CLU_SYNC();
        for (int i = tid; i < SG; i += 1024) gns[i] = g_by1[i];
        __syncthreads();
        for (int r = w; r < R_SG; r += 32) {
            int gr = rank * R_SG + r;
            float s = row_dot<SG>(Wv + (size_t)gr * SG, gns, lane);
            if (lane == 0) g_by2[gr] = s + bv[gr];
        }
        CLU_SYNC();
        for (int i = tid; i < SG; i += 1024) vvs[i] = g_by2[i];
        __syncthreads();
        for (int r = w; r < R_SG; r += 32) {
            int gr = rank * R_SG + r;
            float s = row_dot<SG>(Wo + (size_t)gr * SG, vvs, lane);
            if (lane == 0) g_by1[gr] = gns[gr] + (s + bo[gr]);
        }
        CLU_SYNC();
        for (int i = tid; i < SG; i += 1024) ys[i] = g_by1[i];
        __syncthreads();
        layernorm256(ys, xs, ln1g, ln1b, tid, red);
        for (int r = w; r < R_FF; r += 32) {
            int gr = rank * R_FF + r;
            float s = row_dot<SG>(Wf1 + (size_t)gr * SG, xs, lane);
            if (lane == 0) g_bff[gr] = fmaxf(s + bf1[gr], 0.f);
        }
        CLU_SYNC();
        for (int i = tid; i < DFF; i += 1024) ff1s[i] = g_bff[i];
        __syncthreads();
        for (int r = w; r < R_SG; r += 32) {
            int gr = rank * R_SG + r;
            float s = row_dot<DFF>(Wf2 + (size_t)gr * DFF, ff1s, lane);
            if (lane == 0) g_by2[gr] = xs[gr] + (s + bf2[gr]);
        }
        CLU_SYNC();
        for (int i = tid; i < SG; i += 1024) ys[i] = g_by2[i];
        __syncthreads();
        layernorm256(ys, cat + 256, ln2g, ln2b, tid, red);
    }
}

// ---------------------------------------------------------------------------
// Sampler: T=8 timesteps per block (bit-exact probs path given h).
// ---------------------------------------------------------------------------
#define SAMP_T 8
#define SAMP_THREADS 512
#define SAMP_SMEM ((SAMP_T * SG + SAMP_T * NROW) * 4)

__global__ void __launch_bounds__(SAMP_THREADS) sample_kernel8(
    const float* __restrict__ u,
    const float* __restrict__ Wr, const float* __restrict__ br,
    float* __restrict__ out) {
    extern __shared__ __align__(16) float sm[];
    float* hsm = sm;
    float* probs = sm + SAMP_T * SG;
    __shared__ int cnt[SAMP_T][4];
    __shared__ int sel[SAMP_T];

    int tb = blockIdx.x * SAMP_T;
    int tid = threadIdx.x, w = tid >> 5, lane = tid & 31;

    for (int i = tid; i < SAMP_T * SG; i += SAMP_THREADS)
        hsm[i] = g_h_all[(size_t)tb * SG + i];
    if (tid < SAMP_T * 4) cnt[tid >> 2][tid & 3] = 0;
    __syncthreads();

    for (int r = w; r < NROW; r += 16) {
        const float* Wrow = Wr + (size_t)r * SG;
        float brv = br[r];
#pragma unroll
        for (int j = 0; j < SAMP_T; ++j) {
            float s = row_dot<SG>(Wrow, hsm + j * SG, lane);
            if (lane == 0) {
                float z = s + brv;
                float p;
                if (z >= 0.f) {
                    p = 1.f / (1.f + expf(-z));
                } else {
                    float e = expf(z);
                    p = e / (1.f + e);
                }
                probs[j * NROW + r] = p;
            }
        }
    }
    __syncthreads();

#pragma unroll
    for (int j = 0; j < SAMP_T; ++j) {
        const float* __restrict__ ut = u + (size_t)(tb + j) * 4 * NROW;
        int c[4] = {0, 0, 0, 0};
#pragma unroll
        for (int k = 0; k < 4; ++k)
#pragma unroll
            for (int i = 0; i < NROW / SAMP_THREADS; ++i) {
                int n = tid + SAMP_THREADS * i;
                c[k] += (ut[k * NROW + n] < probs[j * NROW + n]) ? 1 : 0;
            }
#pragma unroll
        for (int k = 0; k < 4; ++k) {
            int s = c[k];
#pragma unroll
            for (int o = 16; o; o >>= 1) s += __shfl_xor_sync(0xffffffffu, s, o);
            if (lane == 0) atomicAdd(&cnt[j][k], s);
        }
    }
    __syncthreads();

    if (tid < SAMP_T) {
        int idx = 0;
        for (int k = 3; k >= 0; --k) {
            int ck = cnt[tid][k];
            bool valid = (ck == 0) || (ck >= 2 && ck <= 6);
            if (valid) idx = k;
        }
        sel[tid] = idx;
    }
    __syncthreads();

#pragma unroll
    for (int j = 0; j < SAMP_T; ++j) {
        const float* __restrict__ ut = u + (size_t)(tb + j) * 4 * NROW;
        int idx = sel[j];
#pragma unroll
        for (int i = 0; i < NROW / SAMP_THREADS; ++i) {
            int n = tid + SAMP_THREADS * i;
            out[(size_t)(tb + j) * NROW + n] =
                (ut[idx * NROW + n] < probs[j * NROW + n]) ? 1.f : 0.f;
        }
    }
}

extern "C" void kernel_launch(void* const* d_in, const int* in_sizes, int n_in,
                              void* d_out, int out_size) {
    (void)in_sizes; (void)n_in; (void)out_size;
    const float* gnn  = (const float*)d_in[0];
    const float* u    = (const float*)d_in[2];
    const float* W1   = (const float*)d_in[3];
    const float* b1   = (const float*)d_in[4];
    const float* W2   = (const float*)d_in[5];
    const float* b2   = (const float*)d_in[6];
    const float* Wr   = (const float*)d_in[7];
    const float* br   = (const float*)d_in[8];
    const float* Wg   = (const float*)d_in[9];
    const float* bg   = (const float*)d_in[10];
    const float* Wv   = (const float*)d_in[11];
    const float* bv   = (const float*)d_in[12];
    const float* Wo   = (const float*)d_in[13];
    const float* bo   = (const float*)d_in[14];
    const float* Wf1  = (const float*)d_in[15];
    const float* bf1  = (const float*)d_in[16];
    const float* Wf2  = (const float*)d_in[17];
    const float* bf2  = (const float*)d_in[18];
    const float* ln1g = (const float*)d_in[19];
    const float* ln1b = (const float*)d_in[20];
    const float* ln2g = (const float*)d_in[21];
    const float* ln2b = (const float*)d_in[22];

    // fold the linear sub-chain (deterministic, every call)
    fold1<<<SG, SG>>>(Wo, Wv);
    fold2<<<SG, SG>>>(Wg, bg, Wo, bv, bo);
    fold3<<<SG, H1DIM>>>(W2, b2);

    cudaFuncSetAttribute(seq2_kernel,
                         cudaFuncAttributeMaxDynamicSharedMemorySize, SEQ2_SMEM_BYTES);
    cudaFuncSetAttribute(seq2_kernel,
                         cudaFuncAttributeNonPortableClusterSizeAllowed, 1);

    cudaError_t e = cudaErrorUnknown;
    {
        cudaLaunchConfig_t cfg = {};
        cfg.gridDim = dim3(16, 1, 1);
        cfg.blockDim = dim3(512, 1, 1);
        cfg.dynamicSmemBytes = SEQ2_SMEM_BYTES;
        cfg.stream = 0;
        cudaLaunchAttribute at[1];
        at[0].id = cudaLaunchAttributeClusterDimension;
        at[0].val.clusterDim.x = 16;
        at[0].val.clusterDim.y = 1;
        at[0].val.clusterDim.z = 1;
        cfg.attrs = at;
        cfg.numAttrs = 1;
        e = cudaLaunchKernelEx(&cfg, seq2_kernel,
                               gnn, W1, b1, W2, b2, Wf1, bf1, Wf2, bf2,
                               ln1g, ln1b, ln2g, ln2b);
    }
    if (e != cudaSuccess) {
        cudaLaunchConfig_t cfg = {};
        cfg.gridDim = dim3(8, 1, 1);
        cfg.blockDim = dim3(1024, 1, 1);
        cfg.dynamicSmemBytes = 0;
        cfg.stream = 0;
        cudaLaunchAttribute at[1];
        at[0].id = cudaLaunchAttributeClusterDimension;
        at[0].val.clusterDim.x = 8;
        at[0].val.clusterDim.y = 1;
        at[0].val.clusterDim.z = 1;
        cfg.attrs = at;
        cfg.numAttrs = 1;
        cudaLaunchKernelEx(&cfg, seq_fallback8,
                           gnn, W1, b1, W2, b2, Wg, bg, Wv, bv, Wo, bo,
                           Wf1, bf1, Wf2, bf2, ln1g, ln1b, ln2g, ln2b);
    }

    cudaFuncSetAttribute(sample_kernel8,
                         cudaFuncAttributeMaxDynamicSharedMemorySize, SAMP_SMEM);
    sample_kernel8<<<NSTEPS / SAMP_T, SAMP_THREADS, SAMP_SMEM>>>(
        u, Wr, br, (float*)d_out);
}

// round 8
// speedup vs baseline: 3.0611x; 1.2229x over previous
#include <cuda_runtime.h>
#include <math.h>

#define NSTEPS 8192
#define NNODES 4096
#define SG 256
#define NROW 2048
#define DFF 2048
#define H1DIM 512

// h_t for every step (consumed by the sampler kernel)
__device__ float g_h_all[NSTEPS * SG];
// folded matrices (recomputed deterministically every launch)
__device__ float g_A[SG * SG];      // Wo @ Wv
__device__ float g_Bm[SG * SG];     // (I + A) @ Wg
__device__ float g_d[SG];           // (I+A)@bg + Wo@bv + bo
__device__ float g_C[SG * H1DIM];   // Bm @ W2
__device__ float g_e[SG];           // Bm @ b2 + d
// cross-CTA partial buffers (L2-resident)
__device__ float g_p1[16 * SG];     // y1 partials
__device__ float g_ph[16 * SG];     // h partials
__device__ float g_p2[16 * SG];     // y2 partials
// fallback broadcast buffers
__device__ float g_bh1[H1DIM];
__device__ float g_by1[SG];
__device__ float g_bff[DFF];
__device__ float g_by2[SG];

#define CLU_SYNC()                                                        \
    do {                                                                  \
        asm volatile("barrier.cluster.arrive.aligned;" ::: "memory");    \
        asm volatile("barrier.cluster.wait.aligned;" ::: "memory");      \
    } while (0)

__device__ __forceinline__ unsigned smem_u32(const void* p) {
    return (unsigned)__cvta_generic_to_shared(p);
}

// remote arrive with release at cluster scope (cumulative: covers all CTA
// stores that are happens-before via the preceding __syncthreads)
__device__ __forceinline__ void arrive_remote_rel(unsigned lmbar, unsigned rank) {
    unsigned r;
    asm volatile("mapa.shared::cluster.u32 %0, %1, %2;" : "=r"(r) : "r"(lmbar), "r"(rank));
    asm volatile("mbarrier.arrive.release.cluster.shared::cluster.b64 _, [%0];"
                 :: "r"(r) : "memory");
}

__device__ __forceinline__ void bar_wait_acq(unsigned mbar, unsigned parity) {
    asm volatile(
        "{\n\t.reg .pred P;\n\t"
        "WL%=:\n\t"
        "mbarrier.try_wait.parity.acquire.cluster.shared::cta.b64 P, [%0], %1, 0x989680;\n\t"
        "@P bra WD%=;\n\t"
        "bra WL%=;\n\t"
        "WD%=:\n\t}"
        :: "r"(mbar), "r"(parity) : "memory");
}

__device__ __forceinline__ float warp_reduce(float v) {
#pragma unroll
    for (int o = 16; o; o >>= 1) v += __shfl_xor_sync(0xffffffffu, v, o);
    return v;
}

template <int C>
__device__ __forceinline__ float row_dot(const float* __restrict__ W,
                                         const float* __restrict__ x, int lane) {
    const float4* __restrict__ W4 = reinterpret_cast<const float4*>(W);
    const float4* __restrict__ x4 = reinterpret_cast<const float4*>(x);
    float s = 0.f;
#pragma unroll
    for (int c = 0; c < C / 4; c += 32) {
        float4 w = W4[c + lane];
        float4 xv = x4[c + lane];
        s += w.x * xv.x + w.y * xv.y + w.z * xv.z + w.w * xv.w;
    }
    return warp_reduce(s);
}

// two-pass LN (fallback kernel only)
__device__ __forceinline__ void layernorm256(const float* __restrict__ y,
                                             float* __restrict__ out,
                                             const float* __restrict__ gma,
                                             const float* __restrict__ bta,
                                             int tid, float* red) {
    int w = tid >> 5, lane = tid & 31;
    if (w == 0) {
        float s = 0.f;
#pragma unroll
        for (int i = 0; i < 8; ++i) s += y[lane + 32 * i];
        s = warp_reduce(s);
        if (lane == 0) red[0] = s * (1.f / 256.f);
    }
    __syncthreads();
    float mu = red[0];
    if (w == 0) {
        float s = 0.f;
#pragma unroll
        for (int i = 0; i < 8; ++i) {
            float d = y[lane + 32 * i] - mu;
            s += d * d;
        }
        s = warp_reduce(s);
        if (lane == 0) red[1] = 1.f / sqrtf(s * (1.f / 256.f) + 1e-5f);
    }
    __syncthreads();
    float inv = red[1];
    if (tid < 256) out[tid] = (y[tid] - mu) * inv * gma[tid] + bta[tid];
    __syncthreads();
}

// ---------------------------------------------------------------------------
// Setup kernels: fold gnew->attn->residual into C, e.
// ---------------------------------------------------------------------------
__global__ void fold1(const float* __restrict__ Wo, const float* __restrict__ Wv) {
    int i = blockIdx.x, j = threadIdx.x;
    float s = 0.f;
    for (int k = 0; k < SG; ++k) s += Wo[i * SG + k] * Wv[k * SG + j];
    g_A[i * SG + j] = s;
}

__global__ void fold2(const float* __restrict__ Wg, const float* __restrict__ bg,
                      const float* __restrict__ Wo, const float* __restrict__ bv,
                      const float* __restrict__ bo) {
    int i = blockIdx.x, j = threadIdx.x;
    float s = Wg[i * SG + j];
    for (int k = 0; k < SG; ++k) s += g_A[i * SG + k] * Wg[k * SG + j];
    g_Bm[i * SG + j] = s;
    if (j == 0) {
        float t = bg[i] + bo[i];
        for (int k = 0; k < SG; ++k) t += g_A[i * SG + k] * bg[k];
        for (int k = 0; k < SG; ++k) t += Wo[i * SG + k] * bv[k];
        g_d[i] = t;
    }
}

__global__ void fold3(const float* __restrict__ W2, const float* __restrict__ b2) {
    int i = blockIdx.x, j = threadIdx.x;
    float s = 0.f;
    for (int k = 0; k < SG; ++k) s += g_Bm[i * SG + k] * W2[k * H1DIM + j];
    g_C[i * H1DIM + j] = s;
    if (j == 0) {
        float t = g_d[i];
        for (int k = 0; k < SG; ++k) t += g_Bm[i * SG + k] * b2[k];
        g_e[i] = t;
    }
}

// ---------------------------------------------------------------------------
// Main chain: 16-CTA cluster, 512 thr/CTA, 2 lightweight mbarrier syncs/step,
// fused single-pass LayerNorms, gnn prefetch.
// ---------------------------------------------------------------------------
#define SEQ3_SMEM_FLOATS (32 * H1DIM + 128 * SG + 512 + 32 + 256 + 128 + 512 + 32)
#define SEQ3_SMEM_BYTES (SEQ3_SMEM_FLOATS * 4)

__global__ void __launch_bounds__(512, 1) seq3_kernel(
    const float* __restrict__ gnn,
    const float* __restrict__ W1, const float* __restrict__ b1,
    const float* __restrict__ W2, const float* __restrict__ b2,
    const float* __restrict__ Wf1, const float* __restrict__ bf1,
    const float* __restrict__ Wf2, const float* __restrict__ bf2,
    const float* __restrict__ ln1g, const float* __restrict__ ln1b,
    const float* __restrict__ ln2g, const float* __restrict__ ln2b) {
    extern __shared__ __align__(16) float sm[];
    float* w1s   = sm;                  // [32][512]  W1 row slice
    float* wf1s  = w1s + 32 * H1DIM;    // [128][256] Wf1 row slice
    float* cat   = wf1s + 128 * SG;     // [m(256); g(256)]
    float* h1loc = cat + 512;           // 32
    float* xs    = h1loc + 32;          // 256
    float* ffloc = xs + 256;            // 128
    float* p2tmp = ffloc + 128;         // 512
    float* redsm = p2tmp + 512;         // 18 used
    __shared__ __align__(8) unsigned long long mb[2];

    int tid = threadIdx.x, w = tid >> 5, lane = tid & 31;
    unsigned rank;
    asm("mov.u32 %0, %%cluster_ctarank;" : "=r"(rank));
    unsigned a_mb = smem_u32(mb);

    // resident smem weights
    {
        const float4* src = reinterpret_cast<const float4*>(W1 + (size_t)rank * 32 * H1DIM);
        float4* dst = reinterpret_cast<float4*>(w1s);
        for (int i = tid; i < 32 * H1DIM / 4; i += 512) dst[i] = src[i];
        src = reinterpret_cast<const float4*>(Wf1 + (size_t)rank * 128 * SG);
        dst = reinterpret_cast<float4*>(wf1s);
        for (int i = tid; i < 128 * SG / 4; i += 512) dst[i] = src[i];
    }

    // persistent register weights
    float pw[32];
    {
        const float* psrc = (tid < 256)
            ? (W2 + (size_t)tid * H1DIM + rank * 32)
            : (g_C + (size_t)(tid - 256) * H1DIM + rank * 32);
#pragma unroll
        for (int c = 0; c < 32; ++c) pw[c] = psrc[c];
    }
    float wf2c[64];
    {
        int r2 = tid & 255, half = tid >> 8;
        const float* wsrc = Wf2 + (size_t)r2 * DFF + rank * 128 + half * 64;
#pragma unroll
        for (int c = 0; c < 64; ++c) wf2c[c] = wsrc[c];
    }
    const int g1a = rank * 32 + w, g1b = g1a + 16;
    float b1a = b1[g1a], b1b = b1[g1b];
    float bf1r[8];
#pragma unroll
    for (int i = 0; i < 8; ++i) bf1r[i] = bf1[rank * 128 + w + 16 * i];
    float e_r = (tid < 256) ? g_e[tid] : 0.f;
    float bf2_r = (tid < 256) ? bf2[tid] : 0.f;
    float l1g = 0.f, l1b_ = 0.f, l2g = 0.f, l2b_ = 0.f;
    if (tid < 256) {
        l1g = ln1g[tid]; l1b_ = ln1b[tid];
        l2g = ln2g[tid]; l2b_ = ln2b[tid];
    }
    float b2row = 0.f;
    int hrow = -1;
    if (tid >= 256 && tid < 256 + 16) {
        hrow = rank * 16 + (tid - 256);
        b2row = b2[hrow];
    }

    if (tid < 2) {
        asm volatile("mbarrier.init.shared.b64 [%0], %1;"
                     :: "r"(a_mb + tid * 8), "r"(16) : "memory");
    }
    if (tid < 256) {
        cat[256 + tid] = 0.f;                              // g0 = 0
        cat[tid] = gnn[(size_t)tid];                       // m_0
    }
    __syncthreads();
    CLU_SYNC();  // mbar inits + weight slices visible before any remote arrive

    for (int t = 0; t < NSTEPS; ++t) {
        unsigned par = (unsigned)(t & 1);

        // prefetch next step's m (off critical path)
        float mnext = 0.f;
        if (tid < 256)
            mnext = gnn[(size_t)((t + 1) & (NNODES - 1)) * SG + tid];

        // S1: h1 slice = relu(W1@[m;g]+b1), 2 rows/warp (smem weights)
        {
            float s0 = row_dot<H1DIM>(w1s + w * H1DIM, cat, lane);
            float v0 = fmaxf(s0 + b1a, 0.f);
            float s1 = row_dot<H1DIM>(w1s + (w + 16) * H1DIM, cat, lane);
            float v1 = fmaxf(s1 + b1b, 0.f);
            if (lane == 0) { h1loc[w] = v0; h1loc[w + 16] = v1; }
        }
        __syncthreads();

        // partial-1: one 32-col dot per thread (h partial / y1 partial)
        {
            float acc = 0.f;
#pragma unroll
            for (int c = 0; c < 32; ++c) acc += pw[c] * h1loc[c];
            if (tid < 256) g_ph[rank * SG + tid] = acc;
            else           g_p1[rank * SG + (tid - 256)] = acc;
        }
        __syncthreads();
        if (tid < 16) arrive_remote_rel(a_mb + 0 * 8, (unsigned)tid);
        bar_wait_acq(a_mb + 0 * 8, par);                   // sync 1

        // reduce y1 (fixed k order) + h rows; y1 stays in register
        float yv = 0.f;
        if (tid < 256) {
            float s = e_r;
#pragma unroll
            for (int k = 0; k < 16; ++k) s += g_p1[k * SG + tid];
            yv = s;
        } else if (hrow >= 0) {
            float s = b2row;
#pragma unroll
            for (int k = 0; k < 16; ++k) s += g_ph[k * SG + hrow];
            g_h_all[(size_t)t * SG + hrow] = s;
        }

        // LN1 fused single-pass: x = LN(yv) -> xs
        if (tid < 256) {
            float s = yv, s2 = yv * yv;
#pragma unroll
            for (int o = 16; o; o >>= 1) {
                s += __shfl_xor_sync(0xffffffffu, s, o);
                s2 += __shfl_xor_sync(0xffffffffu, s2, o);
            }
            if (lane == 0) { redsm[2 * w] = s; redsm[2 * w + 1] = s2; }
        }
        __syncthreads();
        if (tid == 0) {
            float s = 0.f, s2 = 0.f;
#pragma unroll
            for (int i = 0; i < 8; ++i) { s += redsm[2 * i]; s2 += redsm[2 * i + 1]; }
            float mu = s * (1.f / 256.f);
            float var = s2 * (1.f / 256.f) - mu * mu;
            redsm[16] = mu;
            redsm[17] = 1.f / sqrtf(var + 1e-5f);
        }
        __syncthreads();
        if (tid < 256)
            xs[tid] = (yv - redsm[16]) * redsm[17] * l1g + l1b_;
        __syncthreads();

        // ff slice = relu(Wf1@x + bf1), 8 rows/warp (smem weights, CTA-local)
#pragma unroll
        for (int i = 0; i < 8; ++i) {
            int r = w + 16 * i;
            float s = row_dot<SG>(wf1s + r * SG, xs, lane);
            if (lane == 0) ffloc[r] = fmaxf(s + bf1r[i], 0.f);
        }
        __syncthreads();

        // partial-2: y2 partial = Wf2[:, my 128 cols] @ ffloc
        {
            int half = tid >> 8;
            const float* fl = ffloc + half * 64;
            float a2 = 0.f;
#pragma unroll
            for (int c = 0; c < 64; ++c) a2 += wf2c[c] * fl[c];
            p2tmp[tid] = a2;
        }
        __syncthreads();
        if (tid < 256) g_p2[rank * SG + tid] = p2tmp[tid] + p2tmp[tid + 256];
        __syncthreads();
        if (tid < 16) arrive_remote_rel(a_mb + 1 * 8, (unsigned)tid);
        bar_wait_acq(a_mb + 1 * 8, par);                   // sync 2

        // reduce y2 + LN2 fused -> cat[256..511]; write prefetched m
        float y2 = 0.f;
        if (tid < 256) {
            float s = xs[tid] + bf2_r;
#pragma unroll
            for (int k = 0; k < 16; ++k) s += g_p2[k * SG + tid];
            y2 = s;
            float sa = y2, s2a = y2 * y2;
#pragma unroll
            for (int o = 16; o; o >>= 1) {
                sa += __shfl_xor_sync(0xffffffffu, sa, o);
                s2a += __shfl_xor_sync(0xffffffffu, s2a, o);
            }
            if (lane == 0) { redsm[2 * w] = sa; redsm[2 * w + 1] = s2a; }
        }
        __syncthreads();
        if (tid == 0) {
            float s = 0.f, s2 = 0.f;
#pragma unroll
            for (int i = 0; i < 8; ++i) { s += redsm[2 * i]; s2 += redsm[2 * i + 1]; }
            float mu = s * (1.f / 256.f);
            float var = s2 * (1.f / 256.f) - mu * mu;
            redsm[16] = mu;
            redsm[17] = 1.f / sqrtf(var + 1e-5f);
        }
        __syncthreads();
        if (tid < 256) {
            cat[256 + tid] = (y2 - redsm[16]) * redsm[17] * l2g + l2b_;
            cat[tid] = mnext;
        }
        __syncthreads();
    }
    CLU_SYNC();
}

// ---------------------------------------------------------------------------
// Fallback (cluster size < 16): R4-proven streaming kernel, CL=8.
// ---------------------------------------------------------------------------
__global__ void __launch_bounds__(1024, 1) seq_fallback8(
    const float* __restrict__ gnn,
    const float* __restrict__ W1, const float* __restrict__ b1,
    const float* __restrict__ W2, const float* __restrict__ b2,
    const float* __restrict__ Wg, const float* __restrict__ bg,
    const float* __restrict__ Wv, const float* __restrict__ bv,
    const float* __restrict__ Wo, const float* __restrict__ bo,
    const float* __restrict__ Wf1, const float* __restrict__ bf1,
    const float* __restrict__ Wf2, const float* __restrict__ bf2,
    const float* __restrict__ ln1g, const float* __restrict__ ln1b,
    const float* __restrict__ ln2g, const float* __restrict__ ln2b) {
    constexpr int CL = 8;
    constexpr int R_H1 = H1DIM / CL, R_SG = SG / CL, R_FF = DFF / CL;
    __shared__ __align__(16) float cat[H1DIM];
    __shared__ __align__(16) float h1s[H1DIM];
    __shared__ __align__(16) float hs[SG];
    __shared__ __align__(16) float gns[SG];
    __shared__ __align__(16) float vvs[SG];
    __shared__ __align__(16) float ys[SG];
    __shared__ __align__(16) float xs[SG];
    __shared__ __align__(16) float ff1s[DFF];
    __shared__ float red[2];

    int tid = threadIdx.x, w = tid >> 5, lane = tid & 31;
    unsigned rank;
    asm("mov.u32 %0, %%cluster_ctarank;" : "=r"(rank));
    if (tid < 256) cat[256 + tid] = 0.f;
    __syncthreads();

    for (int t = 0; t < NSTEPS; ++t) {
        if (tid < 256) cat[tid] = gnn[(size_t)(t & (NNODES - 1)) * SG + tid];
        __syncthreads();
        for (int r = w; r < R_H1; r += 32) {
            int gr = rank * R_H1 + r;
            float s = row_dot<H1DIM>(W1 + (size_t)gr * H1DIM, cat, lane);
            if (lane == 0) g_bh1[gr] = fmaxf(s + b1[gr], 0.f);
        }
        CLU_SYNC();
        for (int i = tid; i < H1DIM; i += 1024) h1s[i] = g_bh1[i];
        __syncthreads();
        float* gh = g_h_all + (size_t)t * SG;
        for (int r = w; r < R_SG; r += 32) {
            int gr = rank * R_SG + r;
            float s = row_dot<H1DIM>(W2 + (size_t)gr * H1DIM, h1s, lane);
            if (lane == 0) gh[gr] = s + b2[gr];
        }
        CLU_SYNC();
        for (int i = tid; i < SG; i += 1024) hs[i] = gh[i];
        __syncthreads();
        for (int r = w; r < R_SG; r += 32) {
            int gr = rank * R_SG + r;
            float s = row_dot<SG>(Wg + (size_t)gr * SG, hs, lane);
            if (lane == 0) g_by1[gr] = s + bg[gr];
        }
        CLU_SYNC();
        for (int i = tid; i < SG; i += 1024) gns[i] = g_by1[i];
        __syncthreads();
        for (int r = w; r < R_SG; r += 32) {
            int gr = rank * R_SG + r;
            float s = row_dot<SG>(Wv + (size_t)gr * SG, gns, lane);
            if (lane == 0) g_by2[gr] = s + bv[gr];
        }
        CLU_SYNC();
        for (int i = tid; i < SG; i += 1024) vvs[i] = g_by2[i];
        __syncthreads();
        for (int r = w; r < R_SG; r += 32) {
            int gr = rank * R_SG + r;
            float s = row_dot<SG>(Wo + (size_t)gr * SG, vvs, lane);
            if (lane == 0) g_by1[gr] = gns[gr] + (s + bo[gr]);
        }
        CLU_SYNC();
        for (int i = tid; i < SG; i += 1024) ys[i] = g_by1[i];
        __syncthreads();
        layernorm256(ys, xs, ln1g, ln1b, tid, red);
        for (int r = w; r < R_FF; r += 32) {
            int gr = rank * R_FF + r;
            float s = row_dot<SG>(Wf1 + (size_t)gr * SG, xs, lane);
            if (lane == 0) g_bff[gr] = fmaxf(s + bf1[gr], 0.f);
        }
        CLU_SYNC();
        for (int i = tid; i < DFF; i += 1024) ff1s[i] = g_bff[i];
        __syncthreads();
        for (int r = w; r < R_SG; r += 32) {
            int gr = rank * R_SG + r;
            float s = row_dot<DFF>(Wf2 + (size_t)gr * DFF, ff1s, lane);
            if (lane == 0) g_by2[gr] = xs[gr] + (s + bf2[gr]);
        }
        CLU_SYNC();
        for (int i = tid; i < SG; i += 1024) ys[i] = g_by2[i];
        __syncthreads();
        layernorm256(ys, cat + 256, ln2g, ln2b, tid, red);
    }
}

// ---------------------------------------------------------------------------
// Sampler: T=8 timesteps per block.
// ---------------------------------------------------------------------------
#define SAMP_T 8
#define SAMP_THREADS 512
#define SAMP_SMEM ((SAMP_T * SG + SAMP_T * NROW) * 4)

__global__ void __launch_bounds__(SAMP_THREADS) sample_kernel8(
    const float* __restrict__ u,
    const float* __restrict__ Wr, const float* __restrict__ br,
    float* __restrict__ out) {
    extern __shared__ __align__(16) float sm[];
    float* hsm = sm;
    float* probs = sm + SAMP_T * SG;
    __shared__ int cnt[SAMP_T][4];
    __shared__ int sel[SAMP_T];

    int tb = blockIdx.x * SAMP_T;
    int tid = threadIdx.x, w = tid >> 5, lane = tid & 31;

    for (int i = tid; i < SAMP_T * SG; i += SAMP_THREADS)
        hsm[i] = g_h_all[(size_t)tb * SG + i];
    if (tid < SAMP_T * 4) cnt[tid >> 2][tid & 3] = 0;
    __syncthreads();

    for (int r = w; r < NROW; r += 16) {
        const float* Wrow = Wr + (size_t)r * SG;
        float brv = br[r];
#pragma unroll
        for (int j = 0; j < SAMP_T; ++j) {
            float s = row_dot<SG>(Wrow, hsm + j * SG, lane);
            if (lane == 0) {
                float z = s + brv;
                float p;
                if (z >= 0.f) {
                    p = 1.f / (1.f + expf(-z));
                } else {
                    float e = expf(z);
                    p = e / (1.f + e);
                }
                probs[j * NROW + r] = p;
            }
        }
    }
    __syncthreads();

#pragma unroll
    for (int j = 0; j < SAMP_T; ++j) {
        const float* __restrict__ ut = u + (size_t)(tb + j) * 4 * NROW;
        int c[4] = {0, 0, 0, 0};
#pragma unroll
        for (int k = 0; k < 4; ++k)
#pragma unroll
            for (int i = 0; i < NROW / SAMP_THREADS; ++i) {
                int n = tid + SAMP_THREADS * i;
                c[k] += (ut[k * NROW + n] < probs[j * NROW + n]) ? 1 : 0;
            }
#pragma unroll
        for (int k = 0; k < 4; ++k) {
            int s = c[k];
#pragma unroll
            for (int o = 16; o; o >>= 1) s += __shfl_xor_sync(0xffffffffu, s, o);
            if (lane == 0) atomicAdd(&cnt[j][k], s);
        }
    }
    __syncthreads();

    if (tid < SAMP_T) {
        int idx = 0;
        for (int k = 3; k >= 0; --k) {
            int ck = cnt[tid][k];
            bool valid = (ck == 0) || (ck >= 2 && ck <= 6);
            if (valid) idx = k;
        }
        sel[tid] = idx;
    }
    __syncthreads();

#pragma unroll
    for (int j = 0; j < SAMP_T; ++j) {
        const float* __restrict__ ut = u + (size_t)(tb + j) * 4 * NROW;
        int idx = sel[j];
#pragma unroll
        for (int i = 0; i < NROW / SAMP_THREADS; ++i) {
            int n = tid + SAMP_THREADS * i;
            out[(size_t)(tb + j) * NROW + n] =
                (ut[idx * NROW + n] < probs[j * NROW + n]) ? 1.f : 0.f;
        }
    }
}

extern "C" void kernel_launch(void* const* d_in, const int* in_sizes, int n_in,
                              void* d_out, int out_size) {
    (void)in_sizes; (void)n_in; (void)out_size;
    const float* gnn  = (const float*)d_in[0];
    const float* u    = (const float*)d_in[2];
    const float* W1   = (const float*)d_in[3];
    const float* b1   = (const float*)d_in[4];
    const float* W2   = (const float*)d_in[5];
    const float* b2   = (const float*)d_in[6];
    const float* Wr   = (const float*)d_in[7];
    const float* br   = (const float*)d_in[8];
    const float* Wg   = (const float*)d_in[9];
    const float* bg   = (const float*)d_in[10];
    const float* Wv   = (const float*)d_in[11];
    const float* bv   = (const float*)d_in[12];
    const float* Wo   = (const float*)d_in[13];
    const float* bo   = (const float*)d_in[14];
    const float* Wf1  = (const float*)d_in[15];
    const float* bf1  = (const float*)d_in[16];
    const float* Wf2  = (const float*)d_in[17];
    const float* bf2  = (const float*)d_in[18];
    const float* ln1g = (const float*)d_in[19];
    const float* ln1b = (const float*)d_in[20];
    const float* ln2g = (const float*)d_in[21];
    const float* ln2b = (const float*)d_in[22];

    // fold the linear sub-chain (deterministic, every call)
    fold1<<<SG, SG>>>(Wo, Wv);
    fold2<<<SG, SG>>>(Wg, bg, Wo, bv, bo);
    fold3<<<SG, H1DIM>>>(W2, b2);

    cudaFuncSetAttribute(seq3_kernel,
                         cudaFuncAttributeMaxDynamicSharedMemorySize, SEQ3_SMEM_BYTES);
    cudaFuncSetAttribute(seq3_kernel,
                         cudaFuncAttributeNonPortableClusterSizeAllowed, 1);

    cudaError_t e = cudaErrorUnknown;
    {
        cudaLaunchConfig_t cfg = {};
        cfg.gridDim = dim3(16, 1, 1);
        cfg.blockDim = dim3(512, 1, 1);
        cfg.dynamicSmemBytes = SEQ3_SMEM_BYTES;
        cfg.stream = 0;
        cudaLaunchAttribute at[1];
        at[0].id = cudaLaunchAttributeClusterDimension;
        at[0].val.clusterDim.x = 16;
        at[0].val.clusterDim.y = 1;
        at[0].val.clusterDim.z = 1;
        cfg.attrs = at;
        cfg.numAttrs = 1;
        e = cudaLaunchKernelEx(&cfg, seq3_kernel,
                               gnn, W1, b1, W2, b2, Wf1, bf1, Wf2, bf2,
                               ln1g, ln1b, ln2g, ln2b);
    }
    if (e != cudaSuccess) {
        cudaLaunchConfig_t cfg = {};
        cfg.gridDim = dim3(8, 1, 1);
        cfg.blockDim = dim3(1024, 1, 1);
        cfg.dynamicSmemBytes = 0;
        cfg.stream = 0;
        cudaLaunchAttribute at[1];
        at[0].id = cudaLaunchAttributeClusterDimension;
        at[0].val.clusterDim.x = 8;
        at[0].val.clusterDim.y = 1;
        at[0].val.clusterDim.z = 1;
        cfg.attrs = at;
        cfg.numAttrs = 1;
        cudaLaunchKernelEx(&cfg, seq_fallback8,
                           gnn, W1, b1, W2, b2, Wg, bg, Wv, bv, Wo, bo,
                           Wf1, bf1, Wf2, bf2, ln1g, ln1b, ln2g, ln2b);
    }

    cudaFuncSetAttribute(sample_kernel8,
                         cudaFuncAttributeMaxDynamicSharedMemorySize, SAMP_SMEM);
    sample_kernel8<<<NSTEPS / SAMP_T, SAMP_THREADS, SAMP_SMEM>>>(
        u, Wr, br, (float*)d_out);
}

// round 9
// speedup vs baseline: 3.3181x; 1.0840x over previous
#include <cuda_runtime.h>
#include <math.h>

#define NSTEPS 8192
#define NNODES 4096
#define SG 256
#define NROW 2048
#define DFF 2048
#define H1DIM 512

// h_t for every step (consumed by the sampler kernel)
__device__ float g_h_all[NSTEPS * SG];
// folded matrices (recomputed deterministically every launch)
__device__ float g_A[SG * SG];       // Wo @ Wv
__device__ float g_Bm[SG * SG];      // (I + A) @ Wg
__device__ float g_d[SG];            // (I+A)@bg + Wo@bv + bo
__device__ float g_C[SG * H1DIM];    // Bm @ W2
__device__ float g_e[SG];            // Bm @ b2 + d
// LN1 fold: Wf1g = Wf1*diag(ln1g), Rff = rowsum, c1 = Wf1@ln1b + bf1
__device__ float g_wf1g[DFF * SG];
__device__ float g_Rff[DFF];
__device__ float g_c1[DFF];
// LN2 fold into W1 g-columns: W1gg = W1[:,256:]*diag(ln2g), R1 = rowsum,
// k1 = W1[:,256:]@ln2b + b1
__device__ float g_w1gg[H1DIM * SG];
__device__ float g_R1[H1DIM];
__device__ float g_k1[H1DIM];
// cross-CTA partial buffers (L2-resident)
__device__ float g_p1[16 * SG];      // y1 partials
__device__ float g_ph[16 * SG];      // h partials
__device__ float g_p2[16 * SG];      // y2 partials
// fallback broadcast buffers
__device__ float g_bh1[H1DIM];
__device__ float g_by1[SG];
__device__ float g_bff[DFF];
__device__ float g_by2[SG];

#define CLU_SYNC()                                                        \
    do {                                                                  \
        asm volatile("barrier.cluster.arrive.aligned;" ::: "memory");    \
        asm volatile("barrier.cluster.wait.aligned;" ::: "memory");      \
    } while (0)

__device__ __forceinline__ unsigned smem_u32(const void* p) {
    return (unsigned)__cvta_generic_to_shared(p);
}

__device__ __forceinline__ void arrive_remote_rel(unsigned lmbar, unsigned rank) {
    unsigned r;
    asm volatile("mapa.shared::cluster.u32 %0, %1, %2;" : "=r"(r) : "r"(lmbar), "r"(rank));
    asm volatile("mbarrier.arrive.release.cluster.shared::cluster.b64 _, [%0];"
                 :: "r"(r) : "memory");
}

__device__ __forceinline__ void bar_wait_acq(unsigned mbar, unsigned parity) {
    asm volatile(
        "{\n\t.reg .pred P;\n\t"
        "WL%=:\n\t"
        "mbarrier.try_wait.parity.acquire.cluster.shared::cta.b64 P, [%0], %1, 0x989680;\n\t"
        "@P bra WD%=;\n\t"
        "bra WL%=;\n\t"
        "WD%=:\n\t}"
        :: "r"(mbar), "r"(parity) : "memory");
}

__device__ __forceinline__ float warp_reduce(float v) {
#pragma unroll
    for (int o = 16; o; o >>= 1) v += __shfl_xor_sync(0xffffffffu, v, o);
    return v;
}

template <int C>
__device__ __forceinline__ float row_dot(const float* __restrict__ W,
                                         const float* __restrict__ x, int lane) {
    const float4* __restrict__ W4 = reinterpret_cast<const float4*>(W);
    const float4* __restrict__ x4 = reinterpret_cast<const float4*>(x);
    float s = 0.f;
#pragma unroll
    for (int c = 0; c < C / 4; c += 32) {
        float4 w = W4[c + lane];
        float4 xv = x4[c + lane];
        s += w.x * xv.x + w.y * xv.y + w.z * xv.z + w.w * xv.w;
    }
    return warp_reduce(s);
}

// two-pass LN (fallback kernel only)
__device__ __forceinline__ void layernorm256(const float* __restrict__ y,
                                             float* __restrict__ out,
                                             const float* __restrict__ gma,
                                             const float* __restrict__ bta,
                                             int tid, float* red) {
    int w = tid >> 5, lane = tid & 31;
    if (w == 0) {
        float s = 0.f;
#pragma unroll
        for (int i = 0; i < 8; ++i) s += y[lane + 32 * i];
        s = warp_reduce(s);
        if (lane == 0) red[0] = s * (1.f / 256.f);
    }
    __syncthreads();
    float mu = red[0];
    if (w == 0) {
        float s = 0.f;
#pragma unroll
        for (int i = 0; i < 8; ++i) {
            float d = y[lane + 32 * i] - mu;
            s += d * d;
        }
        s = warp_reduce(s);
        if (lane == 0) red[1] = 1.f / sqrtf(s * (1.f / 256.f) + 1e-5f);
    }
    __syncthreads();
    float inv = red[1];
    if (tid < 256) out[tid] = (y[tid] - mu) * inv * gma[tid] + bta[tid];
    __syncthreads();
}

// ---------------------------------------------------------------------------
// Setup kernels
// ---------------------------------------------------------------------------
__global__ void fold1(const float* __restrict__ Wo, const float* __restrict__ Wv) {
    int i = blockIdx.x, j = threadIdx.x;
    float s = 0.f;
    for (int k = 0; k < SG; ++k) s += Wo[i * SG + k] * Wv[k * SG + j];
    g_A[i * SG + j] = s;
}

__global__ void fold2(const float* __restrict__ Wg, const float* __restrict__ bg,
                      const float* __restrict__ Wo, const float* __restrict__ bv,
                      const float* __restrict__ bo) {
    int i = blockIdx.x, j = threadIdx.x;
    float s = Wg[i * SG + j];
    for (int k = 0; k < SG; ++k) s += g_A[i * SG + k] * Wg[k * SG + j];
    g_Bm[i * SG + j] = s;
    if (j == 0) {
        float t = bg[i] + bo[i];
        for (int k = 0; k < SG; ++k) t += g_A[i * SG + k] * bg[k];
        for (int k = 0; k < SG; ++k) t += Wo[i * SG + k] * bv[k];
        g_d[i] = t;
    }
}

__global__ void fold3(const float* __restrict__ W2, const float* __restrict__ b2) {
    int i = blockIdx.x, j = threadIdx.x;
    float s = 0.f;
    for (int k = 0; k < SG; ++k) s += g_Bm[i * SG + k] * W2[k * H1DIM + j];
    g_C[i * H1DIM + j] = s;
    if (j == 0) {
        float t = g_d[i];
        for (int k = 0; k < SG; ++k) t += g_Bm[i * SG + k] * b2[k];
        g_e[i] = t;
    }
}

// LN1 fold into Wf1
__global__ void fold4(const float* __restrict__ Wf1, const float* __restrict__ bf1,
                      const float* __restrict__ ln1g, const float* __restrict__ ln1b) {
    int r = blockIdx.x, j = threadIdx.x;  // DFF blocks x 256 threads
    __shared__ float s1[SG], s2[SG];
    float wv = Wf1[(size_t)r * SG + j];
    float wg = wv * ln1g[j];
    g_wf1g[(size_t)r * SG + j] = wg;
    s1[j] = wg;
    s2[j] = wv * ln1b[j];
    __syncthreads();
    for (int o = 128; o; o >>= 1) {
        if (j < o) { s1[j] += s1[j + o]; s2[j] += s2[j + o]; }
        __syncthreads();
    }
    if (j == 0) { g_Rff[r] = s1[0]; g_c1[r] = s2[0] + bf1[r]; }
}

// LN2 fold into W1 g-columns
__global__ void fold5(const float* __restrict__ W1, const float* __restrict__ b1,
                      const float* __restrict__ ln2g, const float* __restrict__ ln2b) {
    int r = blockIdx.x, j = threadIdx.x;  // H1DIM blocks x 256 threads
    __shared__ float s1[SG], s2[SG];
    float wv = W1[(size_t)r * H1DIM + 256 + j];
    float wg = wv * ln2g[j];
    g_w1gg[(size_t)r * SG + j] = wg;
    s1[j] = wg;
    s2[j] = wv * ln2b[j];
    __syncthreads();
    for (int o = 128; o; o >>= 1) {
        if (j < o) { s1[j] += s1[j + o]; s2[j] += s2[j + o]; }
        __syncthreads();
    }
    if (j == 0) { g_R1[r] = s1[0]; g_k1[r] = s2[0] + b1[r]; }
}

// ---------------------------------------------------------------------------
// Main chain: 16-CTA cluster, 512 thr/CTA, 2 mbarrier syncs/step,
// LN folded into following matvecs, m-dot in sync1 shadow.
// ---------------------------------------------------------------------------
#define SEQ4_SMEM_FLOATS (32 * SG + 32 * SG + 128 * SG + SG + SG + SG + 32 + 128 + 512 + 128 + 128 + 32)
#define SEQ4_SMEM_BYTES (SEQ4_SMEM_FLOATS * 4)

__global__ void __launch_bounds__(512, 1) seq4_kernel(
    const float* __restrict__ gnn,
    const float* __restrict__ W1, const float* __restrict__ b1,
    const float* __restrict__ W2, const float* __restrict__ b2,
    const float* __restrict__ Wf2, const float* __restrict__ bf2,
    const float* __restrict__ ln1g, const float* __restrict__ ln1b) {
    extern __shared__ __align__(16) float sm[];
    float* w1ms  = sm;                  // [32][256]  W1 m-columns slice
    float* w1gs  = w1ms + 32 * SG;      // [32][256]  W1gg slice
    float* wf1s  = w1gs + 32 * SG;      // [128][256] Wf1g slice
    float* mbuf  = wf1s + 128 * SG;     // 256
    float* y1s   = mbuf + SG;           // 256
    float* y2s   = y1s + SG;            // 256 (raw y2)
    float* h1loc = y2s + SG;            // 32
    float* ffloc = h1loc + 32;          // 128
    float* p2tmp = ffloc + 128;         // 512
    float* rffs  = p2tmp + 512;         // 128
    float* c1s   = rffs + 128;          // 128
    float* redsm = c1s + 128;           // 32
    __shared__ __align__(8) unsigned long long mb[2];

    int tid = threadIdx.x, w = tid >> 5, lane = tid & 31;
    unsigned rank;
    asm("mov.u32 %0, %%cluster_ctarank;" : "=r"(rank));
    unsigned a_mb = smem_u32(mb);

    // resident smem weights
    for (int i = tid; i < 32 * SG; i += 512) {
        int r = i >> 8, j = i & 255;
        w1ms[i] = W1[(size_t)(rank * 32 + r) * H1DIM + j];
        w1gs[i] = g_w1gg[(size_t)(rank * 32 + r) * SG + j];
    }
    for (int i = tid; i < 128 * SG; i += 512)
        wf1s[i] = g_wf1g[(size_t)rank * 128 * SG + i];
    if (tid < 128) {
        rffs[tid] = g_Rff[rank * 128 + tid];
        c1s[tid]  = g_c1[rank * 128 + tid];
    }

    // persistent register weights
    float pw[32];
    {
        const float* psrc = (tid < 256)
            ? (W2 + (size_t)tid * H1DIM + rank * 32)
            : (g_C + (size_t)(tid - 256) * H1DIM + rank * 32);
#pragma unroll
        for (int c = 0; c < 32; ++c) pw[c] = psrc[c];
    }
    float wf2c[64];
    {
        int r2 = tid & 255, half = tid >> 8;
        const float* wsrc = Wf2 + (size_t)r2 * DFF + rank * 128 + half * 64;
#pragma unroll
        for (int c = 0; c < 64; ++c) wf2c[c] = wsrc[c];
    }
    const int g1a = rank * 32 + w, g1b = g1a + 16;
    float b1a = b1[g1a], b1b = b1[g1b];
    float R1a = g_R1[g1a], R1b = g_R1[g1b];
    float k1a = g_k1[g1a], k1b = g_k1[g1b];
    float e_r = (tid < 256) ? g_e[tid] : 0.f;
    float bf2_r = (tid < 256) ? bf2[tid] : 0.f;
    float l1g = 0.f, l1b_ = 0.f;
    if (tid < 256) { l1g = ln1g[tid]; l1b_ = ln1b[tid]; }
    float b2row = 0.f;
    int hrow = -1;
    if (tid >= 256 && tid < 256 + 16) {
        hrow = rank * 16 + (tid - 256);
        b2row = b2[hrow];
    }

    if (tid < 2)
        asm volatile("mbarrier.init.shared.b64 [%0], %1;"
                     :: "r"(a_mb + tid * 8), "r"(16) : "memory");
    if (tid < 256) {
        y2s[tid] = 0.f;
        mbuf[tid] = gnn[(size_t)tid];  // m_0
    }
    __syncthreads();
    CLU_SYNC();  // inits + weights visible before any remote arrive

    // initial m-dot (for t=0)
    float md0 = row_dot<SG>(w1ms + w * SG, mbuf, lane);
    float md1 = row_dot<SG>(w1ms + (w + 16) * SG, mbuf, lane);
    float mu1 = 0.f, inv1 = 0.f;

    for (int t = 0; t < NSTEPS; ++t) {
        unsigned par = (unsigned)(t & 1);

        // prefetch m_{t+1}
        float mnext = 0.f;
        if (tid < 256)
            mnext = gnn[(size_t)((t + 1) & (NNODES - 1)) * SG + tid];

        // S1 g-dot over RAW y2 (LN2 folded); concurrent y2-stats finalize
        float dg0 = row_dot<SG>(w1gs + w * SG, y2s, lane);
        float dg1 = row_dot<SG>(w1gs + (w + 16) * SG, y2s, lane);
        if (t > 0 && tid == 0) {
            float s = 0.f, s2 = 0.f;
#pragma unroll
            for (int i = 0; i < 8; ++i) { s += redsm[2 * i]; s2 += redsm[2 * i + 1]; }
            float mu = s * (1.f / 256.f);
            float var = s2 * (1.f / 256.f) - mu * mu;
            redsm[16] = mu;
            redsm[17] = 1.f / sqrtf(var + 1e-5f);
        }
        __syncthreads();

        // S1 epilogue -> h1 slice
        {
            float v0, v1;
            if (t == 0) {
                v0 = md0 + b1a;
                v1 = md1 + b1b;
            } else {
                float mu2 = redsm[16], inv2 = redsm[17];
                v0 = md0 + inv2 * (dg0 - mu2 * R1a) + k1a;
                v1 = md1 + inv2 * (dg1 - mu2 * R1b) + k1b;
            }
            if (lane == 0) {
                h1loc[w] = fmaxf(v0, 0.f);
                h1loc[w + 16] = fmaxf(v1, 0.f);
            }
        }
        __syncthreads();

        // p1 partials; stash m_{t+1} for shadow m-dot
        {
            float acc = 0.f;
#pragma unroll
            for (int c = 0; c < 32; ++c) acc += pw[c] * h1loc[c];
            if (tid < 256) g_ph[rank * SG + tid] = acc;
            else           g_p1[rank * SG + (tid - 256)] = acc;
        }
        if (tid < 256) mbuf[tid] = mnext;
        __syncthreads();
        if (tid < 16) arrive_remote_rel(a_mb + 0 * 8, (unsigned)tid);

        // shadow: m-dot for t+1 (independent of recurrence)
        md0 = row_dot<SG>(w1ms + w * SG, mbuf, lane);
        md1 = row_dot<SG>(w1ms + (w + 16) * SG, mbuf, lane);

        bar_wait_acq(a_mb + 0 * 8, par);                   // sync 1

        // reduce y1 (+ warp stats); h rows
        float y1v = 0.f;
        if (tid < 256) {
            float s = e_r;
#pragma unroll
            for (int k = 0; k < 16; ++k) s += g_p1[k * SG + tid];
            y1v = s;
            y1s[tid] = s;
            float sa = s, s2a = s * s;
#pragma unroll
            for (int o = 16; o; o >>= 1) {
                sa += __shfl_xor_sync(0xffffffffu, sa, o);
                s2a += __shfl_xor_sync(0xffffffffu, s2a, o);
            }
            if (lane == 0) { redsm[2 * w] = sa; redsm[2 * w + 1] = s2a; }
        } else if (hrow >= 0) {
            float s = b2row;
#pragma unroll
            for (int k = 0; k < 16; ++k) s += g_ph[k * SG + hrow];
            g_h_all[(size_t)t * SG + hrow] = s;
        }
        __syncthreads();

        // z = Wf1g @ y1 (raw), concurrent LN1 stats finalize
        float z[8];
#pragma unroll
        for (int i = 0; i < 8; ++i)
            z[i] = row_dot<SG>(wf1s + (w + 16 * i) * SG, y1s, lane);
        if (tid == 0) {
            float s = 0.f, s2 = 0.f;
#pragma unroll
            for (int i = 0; i < 8; ++i) { s += redsm[2 * i]; s2 += redsm[2 * i + 1]; }
            float mu = s * (1.f / 256.f);
            float var = s2 * (1.f / 256.f) - mu * mu;
            redsm[16] = mu;
            redsm[17] = 1.f / sqrtf(var + 1e-5f);
        }
        __syncthreads();

        mu1 = redsm[16];
        inv1 = redsm[17];
        // ff epilogue (LN1 fold)
        if (lane == 0) {
#pragma unroll
            for (int i = 0; i < 8; ++i) {
                int r = w + 16 * i;
                ffloc[r] = fmaxf(inv1 * (z[i] - mu1 * rffs[r]) + c1s[r], 0.f);
            }
        }
        __syncthreads();

        // p2 partials
        {
            int half = tid >> 8;
            const float* fl = ffloc + half * 64;
            float a2 = 0.f;
#pragma unroll
            for (int c = 0; c < 64; ++c) a2 += wf2c[c] * fl[c];
            p2tmp[tid] = a2;
        }
        __syncthreads();
        if (tid < 256) g_p2[rank * SG + tid] = p2tmp[tid] + p2tmp[tid + 256];
        __syncthreads();
        if (tid < 16) arrive_remote_rel(a_mb + 1 * 8, (unsigned)tid);
        bar_wait_acq(a_mb + 1 * 8, par);                   // sync 2

        // reduce y2 raw = x + ffpart + bf2  (x recomputed from y1 regs)
        if (tid < 256) {
            float x = (y1v - mu1) * inv1 * l1g + l1b_;
            float s = x + bf2_r;
#pragma unroll
            for (int k = 0; k < 16; ++k) s += g_p2[k * SG + tid];
            y2s[tid] = s;
            float sa = s, s2a = s * s;
#pragma unroll
            for (int o = 16; o; o >>= 1) {
                sa += __shfl_xor_sync(0xffffffffu, sa, o);
                s2a += __shfl_xor_sync(0xffffffffu, s2a, o);
            }
            if (lane == 0) { redsm[2 * w] = sa; redsm[2 * w + 1] = s2a; }
        }
        __syncthreads();
    }
    CLU_SYNC();
}

// ---------------------------------------------------------------------------
// Fallback (cluster size < 16): R4-proven streaming kernel, CL=8.
// ---------------------------------------------------------------------------
__global__ void __launch_bounds__(1024, 1) seq_fallback8(
    const float* __restrict__ gnn,
    const float* __restrict__ W1, const float* __restrict__ b1,
    const float* __restrict__ W2, const float* __restrict__ b2,
    const float* __restrict__ Wg, const float* __restrict__ bg,
    const float* __restrict__ Wv, const float* __restrict__ bv,
    const float* __restrict__ Wo, const float* __restrict__ bo,
    const float* __restrict__ Wf1, const float* __restrict__ bf1,
    const float* __restrict__ Wf2, const float* __restrict__ bf2,
    const float* __restrict__ ln1g, const float* __restrict__ ln1b,
    const float* __restrict__ ln2g, const float* __restrict__ ln2b) {
    constexpr int CL = 8;
    constexpr int R_H1 = H1DIM / CL, R_SG = SG / CL, R_FF = DFF / CL;
    __shared__ __align__(16) float cat[H1DIM];
    __shared__ __align__(16) float h1s[H1DIM];
    __shared__ __align__(16) float hs[SG];
    __shared__ __align__(16) float gns[SG];
    __shared__ __align__(16) float vvs[SG];
    __shared__ __align__(16) float ys[SG];
    __shared__ __align__(16) float xs[SG];
    __shared__ __align__(16) float ff1s[DFF];
    __shared__ float red[2];

    int tid = threadIdx.x, w = tid >> 5, lane = tid & 31;
    unsigned rank;
    asm("mov.u32 %0, %%cluster_ctarank;" : "=r"(rank));
    if (tid < 256) cat[256 + tid] = 0.f;
    __syncthreads();

    for (int t = 0; t < NSTEPS; ++t) {
        if (tid < 256) cat[tid] = gnn[(size_t)(t & (NNODES - 1)) * SG + tid];
        __syncthreads();
        for (int r = w; r < R_H1; r += 32) {
            int gr = rank * R_H1 + r;
            float s = row_dot<H1DIM>(W1 + (size_t)gr * H1DIM, cat, lane);
            if (lane == 0) g_bh1[gr] = fmaxf(s + b1[gr], 0.f);
        }
        CLU_SYNC();
        for (int i = tid; i < H1DIM; i += 1024) h1s[i] = g_bh1[i];
        __syncthreads();
        float* gh = g_h_all + (size_t)t * SG;
        for (int r = w; r < R_SG; r += 32) {
            int gr = rank * R_SG + r;
            float s = row_dot<H1DIM>(W2 + (size_t)gr * H1DIM, h1s, lane);
            if (lane == 0) gh[gr] = s + b2[gr];
        }
        CLU_SYNC();
        for (int i = tid; i < SG; i += 1024) hs[i] = gh[i];
        __syncthreads();
        for (int r = w; r < R_SG; r += 32) {
            int gr = rank * R_SG + r;
            float s = row_dot<SG>(Wg + (size_t)gr * SG, hs, lane);
            if (lane == 0) g_by1[gr] = s + bg[gr];
        }
        CLU_SYNC();
        for (int i = tid; i < SG; i += 1024) gns[i] = g_by1[i];
        __syncthreads();
        for (int r = w; r < R_SG; r += 32) {
            int gr = rank * R_SG + r;
            float s = row_dot<SG>(Wv + (size_t)gr * SG, gns, lane);
            if (lane == 0) g_by2[gr] = s + bv[gr];
        }
        CLU_SYNC();
        for (int i = tid; i < SG; i += 1024) vvs[i] = g_by2[i];
        __syncthreads();
        for (int r = w; r < R_SG; r += 32) {
            int gr = rank * R_SG + r;
            float s = row_dot<SG>(Wo + (size_t)gr * SG, vvs, lane);
            if (lane == 0) g_by1[gr] = gns[gr] + (s + bo[gr]);
        }
        CLU_SYNC();
        for (int i = tid; i < SG; i += 1024) ys[i] = g_by1[i];
        __syncthreads();
        layernorm256(ys, xs, ln1g, ln1b, tid, red);
        for (int r = w; r < R_FF; r += 32) {
            int gr = rank * R_FF + r;
            float s = row_dot<SG>(Wf1 + (size_t)gr * SG, xs, lane);
            if (lane == 0) g_bff[gr] = fmaxf(s + bf1[gr], 0.f);
        }
        CLU_SYNC();
        for (int i = tid; i < DFF; i += 1024) ff1s[i] = g_bff[i];
        __syncthreads();
        for (int r = w; r < R_SG; r += 32) {
            int gr = rank * R_SG + r;
            float s = row_dot<DFF>(Wf2 + (size_t)gr * DFF, ff1s, lane);
            if (lane == 0) g_by2[gr] = xs[gr] + (s + bf2[gr]);
        }
        CLU_SYNC();
        for (int i = tid; i < SG; i += 1024) ys[i] = g_by2[i];
        __syncthreads();
        layernorm256(ys, cat + 256, ln2g, ln2b, tid, red);
    }
}

// ---------------------------------------------------------------------------
// Sampler: T=8 timesteps per block.
// ---------------------------------------------------------------------------
#define SAMP_T 8
#define SAMP_THREADS 512
#define SAMP_SMEM ((SAMP_T * SG + SAMP_T * NROW) * 4)

__global__ void __launch_bounds__(SAMP_THREADS) sample_kernel8(
    const float* __restrict__ u,
    const float* __restrict__ Wr, const float* __restrict__ br,
    float* __restrict__ out) {
    extern __shared__ __align__(16) float sm[];
    float* hsm = sm;
    float* probs = sm + SAMP_T * SG;
    __shared__ int cnt[SAMP_T][4];
    __shared__ int sel[SAMP_T];

    int tb = blockIdx.x * SAMP_T;
    int tid = threadIdx.x, w = tid >> 5, lane = tid & 31;

    for (int i = tid; i < SAMP_T * SG; i += SAMP_THREADS)
        hsm[i] = g_h_all[(size_t)tb * SG + i];
    if (tid < SAMP_T * 4) cnt[tid >> 2][tid & 3] = 0;
    __syncthreads();

    for (int r = w; r < NROW; r += 16) {
        const float* Wrow = Wr + (size_t)r * SG;
        float brv = br[r];
#pragma unroll
        for (int j = 0; j < SAMP_T; ++j) {
            float s = row_dot<SG>(Wrow, hsm + j * SG, lane);
            if (lane == 0) {
                float z = s + brv;
                float p;
                if (z >= 0.f) {
                    p = 1.f / (1.f + expf(-z));
                } else {
                    float e = expf(z);
                    p = e / (1.f + e);
                }
                probs[j * NROW + r] = p;
            }
        }
    }
    __syncthreads();

#pragma unroll
    for (int j = 0; j < SAMP_T; ++j) {
        const float* __restrict__ ut = u + (size_t)(tb + j) * 4 * NROW;
        int c[4] = {0, 0, 0, 0};
#pragma unroll
        for (int k = 0; k < 4; ++k)
#pragma unroll
            for (int i = 0; i < NROW / SAMP_THREADS; ++i) {
                int n = tid + SAMP_THREADS * i;
                c[k] += (ut[k * NROW + n] < probs[j * NROW + n]) ? 1 : 0;
            }
#pragma unroll
        for (int k = 0; k < 4; ++k) {
            int s = c[k];
#pragma unroll
            for (int o = 16; o; o >>= 1) s += __shfl_xor_sync(0xffffffffu, s, o);
            if (lane == 0) atomicAdd(&cnt[j][k], s);
        }
    }
    __syncthreads();

    if (tid < SAMP_T) {
        int idx = 0;
        for (int k = 3; k >= 0; --k) {
            int ck = cnt[tid][k];
            bool valid = (ck == 0) || (ck >= 2 && ck <= 6);
            if (valid) idx = k;
        }
        sel[tid] = idx;
    }
    __syncthreads();

#pragma unroll
    for (int j = 0; j < SAMP_T; ++j) {
        const float* __restrict__ ut = u + (size_t)(tb + j) * 4 * NROW;
        int idx = sel[j];
#pragma unroll
        for (int i = 0; i < NROW / SAMP_THREADS; ++i) {
            int n = tid + SAMP_THREADS * i;
            out[(size_t)(tb + j) * NROW + n] =
                (ut[idx * NROW + n] < probs[j * NROW + n]) ? 1.f : 0.f;
        }
    }
}

extern "C" void kernel_launch(void* const* d_in, const int* in_sizes, int n_in,
                              void* d_out, int out_size) {
    (void)in_sizes; (void)n_in; (void)out_size;
    const float* gnn  = (const float*)d_in[0];
    const float* u    = (const float*)d_in[2];
    const float* W1   = (const float*)d_in[3];
    const float* b1   = (const float*)d_in[4];
    const float* W2   = (const float*)d_in[5];
    const float* b2   = (const float*)d_in[6];
    const float* Wr   = (const float*)d_in[7];
    const float* br   = (const float*)d_in[8];
    const float* Wg   = (const float*)d_in[9];
    const float* bg   = (const float*)d_in[10];
    const float* Wv   = (const float*)d_in[11];
    const float* bv   = (const float*)d_in[12];
    const float* Wo   = (const float*)d_in[13];
    const float* bo   = (const float*)d_in[14];
    const float* Wf1  = (const float*)d_in[15];
    const float* bf1  = (const float*)d_in[16];
    const float* Wf2  = (const float*)d_in[17];
    const float* bf2  = (const float*)d_in[18];
    const float* ln1g = (const float*)d_in[19];
    const float* ln1b = (const float*)d_in[20];
    const float* ln2g = (const float*)d_in[21];
    const float* ln2b = (const float*)d_in[22];

    // folds (deterministic, every call)
    fold1<<<SG, SG>>>(Wo, Wv);
    fold2<<<SG, SG>>>(Wg, bg, Wo, bv, bo);
    fold3<<<SG, H1DIM>>>(W2, b2);
    fold4<<<DFF, SG>>>(Wf1, bf1, ln1g, ln1b);
    fold5<<<H1DIM, SG>>>(W1, b1, ln2g, ln2b);

    cudaFuncSetAttribute(seq4_kernel,
                         cudaFuncAttributeMaxDynamicSharedMemorySize, SEQ4_SMEM_BYTES);
    cudaFuncSetAttribute(seq4_kernel,
                         cudaFuncAttributeNonPortableClusterSizeAllowed, 1);

    cudaError_t e = cudaErrorUnknown;
    {
        cudaLaunchConfig_t cfg = {};
        cfg.gridDim = dim3(16, 1, 1);
        cfg.blockDim = dim3(512, 1, 1);
        cfg.dynamicSmemBytes = SEQ4_SMEM_BYTES;
        cfg.stream = 0;
        cudaLaunchAttribute at[1];
        at[0].id = cudaLaunchAttributeClusterDimension;
        at[0].val.clusterDim.x = 16;
        at[0].val.clusterDim.y = 1;
        at[0].val.clusterDim.z = 1;
        cfg.attrs = at;
        cfg.numAttrs = 1;
        e = cudaLaunchKernelEx(&cfg, seq4_kernel,
                               gnn, W1, b1, W2, b2, Wf2, bf2, ln1g, ln1b);
    }
    if (e != cudaSuccess) {
        cudaLaunchConfig_t cfg = {};
        cfg.gridDim = dim3(8, 1, 1);
        cfg.blockDim = dim3(1024, 1, 1);
        cfg.dynamicSmemBytes = 0;
        cfg.stream = 0;
        cudaLaunchAttribute at[1];
        at[0].id = cudaLaunchAttributeClusterDimension;
        at[0].val.clusterDim.x = 8;
        at[0].val.clusterDim.y = 1;
        at[0].val.clusterDim.z = 1;
        cfg.attrs = at;
        cfg.numAttrs = 1;
        cudaLaunchKernelEx(&cfg, seq_fallback8,
                           gnn, W1, b1, W2, b2, Wg, bg, Wv, bv, Wo, bo,
                           Wf1, bf1, Wf2, bf2, ln1g, ln1b, ln2g, ln2b);
    }

    cudaFuncSetAttribute(sample_kernel8,
                         cudaFuncAttributeMaxDynamicSharedMemorySize, SAMP_SMEM);
    sample_kernel8<<<NSTEPS / SAMP_T, SAMP_THREADS, SAMP_SMEM>>>(
        u, Wr, br, (float*)d_out);
}